// round 5
// baseline (speedup 1.0000x reference)
#include <cuda_runtime.h>
#include <cstdint>

#define PI_F 3.14159265358979323846f
static __device__ float2 g_A[33554432];   // forward spectrum (x<=128 cols valid)
static __device__ float2 g_B[33554432];   // inverse pipeline
static __device__ float2 g_C[16777216];   // 2x2-averaged planes: [b][izu<128][jy][jx]

__device__ __forceinline__ float2 cmul(float2 a, float2 b){
    return make_float2(a.x*b.x - a.y*b.y, a.x*b.y + a.y*b.x);
}
// base-4 digit reversal of an 8-bit index
__device__ __forceinline__ int drev4(int i){
    return ((i & 3) << 6) | (((i >> 2) & 3) << 4) | (((i >> 4) & 3) << 2) | ((i >> 6) & 3);
}

// First NSTAGES stages (L=1,4,16,...) of a 256-pt radix-4 DIT FFT in shared.
// Input stored drev4-ordered. NT threads per line.
template<int SIGN, int NT, int NSTAGES>
__device__ __forceinline__ void fft256_r4s(float2* s, int t){
#pragma unroll
    for (int st = 0; st < NSTAGES; ++st){
        int L = 1 << (2*st);
        __syncthreads();
#pragma unroll
        for (int k = 0; k < 64/NT; ++k){
            int j = t + k*NT;
            int p = j & (L - 1);
            int base = ((j >> (2*st)) << (2*st + 2)) + p;
            float ang = (float)SIGN * (2.0f*PI_F) * (float)p / (float)(4*L);
            float sn, cs; __sincosf(ang, &sn, &cs);
            float2 w1 = make_float2(cs, sn);
            float2 w2 = make_float2(cs*cs - sn*sn, 2.0f*cs*sn);
            float2 w3 = cmul(w1, w2);
            float2 a0 = s[base];
            float2 a1 = cmul(w1, s[base + L]);
            float2 a2 = cmul(w2, s[base + 2*L]);
            float2 a3 = cmul(w3, s[base + 3*L]);
            float2 t02p = make_float2(a0.x + a2.x, a0.y + a2.y);
            float2 t02m = make_float2(a0.x - a2.x, a0.y - a2.y);
            float2 t13p = make_float2(a1.x + a3.x, a1.y + a3.y);
            float2 t13m = make_float2(a1.x - a3.x, a1.y - a3.y);
            float2 jt = (SIGN < 0) ? make_float2(t13m.y, -t13m.x)
                                   : make_float2(-t13m.y, t13m.x);
            s[base]       = make_float2(t02p.x + t13p.x, t02p.y + t13p.y);
            s[base + L]   = make_float2(t02m.x + jt.x,   t02m.y + jt.y);
            s[base + 2*L] = make_float2(t02p.x - t13p.x, t02p.y - t13p.y);
            s[base + 3*L] = make_float2(t02m.x - jt.x,   t02m.y - jt.y);
        }
    }
    __syncthreads();
}

// Last stage (L=64) computed in registers from shared. Butterfly j in [0,64).
template<int SIGN>
__device__ __forceinline__ void fft256_last(const float2* s, int j,
        float2& o0, float2& o1, float2& o2, float2& o3){
    float ang = (float)SIGN * (2.0f*PI_F) * (float)j * (1.0f/256.0f);
    float sn, cs; __sincosf(ang, &sn, &cs);
    float2 w1 = make_float2(cs, sn);
    float2 w2 = make_float2(cs*cs - sn*sn, 2.0f*cs*sn);
    float2 w3 = cmul(w1, w2);
    float2 a0 = s[j];
    float2 a1 = cmul(w1, s[j + 64]);
    float2 a2 = cmul(w2, s[j + 128]);
    float2 a3 = cmul(w3, s[j + 192]);
    float2 t02p = make_float2(a0.x + a2.x, a0.y + a2.y);
    float2 t02m = make_float2(a0.x - a2.x, a0.y - a2.y);
    float2 t13p = make_float2(a1.x + a3.x, a1.y + a3.y);
    float2 t13m = make_float2(a1.x - a3.x, a1.y - a3.y);
    float2 jt = (SIGN < 0) ? make_float2(t13m.y, -t13m.x)
                           : make_float2(-t13m.y, t13m.x);
    o0 = make_float2(t02p.x + t13p.x, t02p.y + t13p.y);
    o1 = make_float2(t02m.x + jt.x,   t02m.y + jt.y);
    o2 = make_float2(t02p.x - t13p.x, t02p.y - t13p.y);
    o3 = make_float2(t02m.x - jt.x,   t02m.y - jt.y);
}

// Forward X + prep: v = sqrt(relu(in*(z/127)^2)), pad to 256, store x<=128 only.
// Block: 4 lines x 64 threads.
__global__ void k_fwd_x(const float* __restrict__ in){
    __shared__ float2 s[4*256];
    int tid = threadIdx.x;
    int l = tid >> 6, t = tid & 63;
    int y = (blockIdx.x << 2) + l;
    int zz = blockIdx.y, b = blockIdx.z;
    float g = (float)zz * (1.0f/127.0f);
    float g2 = g*g;
    const float* row = in + (((size_t)b*128 + zz)*128 + y)*128;
    float2* sl = s + (l << 8);
#pragma unroll
    for (int k = 0; k < 4; ++k){
        int j = t + (k << 6);
        int src = drev4(j);
        float v = 0.0f;
        if (src < 128) v = sqrtf(fmaxf(row[src]*g2, 0.0f));
        sl[j] = make_float2(v, 0.0f);
    }
    fft256_r4s<-1,64,3>(sl, t);
    float2 o0,o1,o2,o3;
    fft256_last<-1>(sl, t, o0,o1,o2,o3);
    float2* outl = g_A + (((size_t)b*256 + zz)*256 + y)*256;
    outl[t]      = o0;
    outl[t + 64] = o1;
    if (t == 0) outl[128] = o2;
}

// Forward Y: x columns [0,128]. Read y<128 (zero-pad), write all 256 y.
__global__ void k_fwd_y(){
    __shared__ float2 s[16*257];
    int x0 = blockIdx.x << 4, zz = blockIdx.y, b = blockIdx.z;
    int tid = threadIdx.x, xl = tid & 15, u = tid >> 4;
    bool valid = (x0 + xl) <= 128;
    float2* base = g_A + ((size_t)b << 24) + ((size_t)zz << 16) + x0;
    float2* sl = s + xl*257;
#pragma unroll
    for (int c = 0; c < 8; ++c){
        int yy = (c << 4) + u;
        float2 v = make_float2(0.f, 0.f);
        if (valid) v = base[(size_t)yy*256 + xl];
        sl[drev4(yy)]       = v;
        sl[drev4(yy + 128)] = make_float2(0.f, 0.f);
    }
    fft256_r4s<-1,16,3>(sl, u);
    if (valid){
#pragma unroll
        for (int k = 0; k < 4; ++k){
            int j = (k << 4) + u;
            float2 o0,o1,o2,o3;
            fft256_last<-1>(sl, j, o0,o1,o2,o3);
            base[(size_t)j*256 + xl]         = o0;
            base[(size_t)(j + 64)*256 + xl]  = o1;
            base[(size_t)(j + 128)*256 + xl] = o2;
            base[(size_t)(j + 192)*256 + xl] = o3;
        }
    }
}

// Forward Z: x columns [0,128]. Read z<128 (zero-pad), write all 256 z.
__global__ void k_fwd_z(){
    __shared__ float2 s[16*257];
    int x0 = blockIdx.x << 4, y = blockIdx.y, b = blockIdx.z;
    int tid = threadIdx.x, xl = tid & 15, u = tid >> 4;
    bool valid = (x0 + xl) <= 128;
    float2* base = g_A + ((size_t)b << 24) + ((size_t)y << 8) + x0;
    float2* sl = s + xl*257;
#pragma unroll
    for (int c = 0; c < 8; ++c){
        int zz = (c << 4) + u;
        float2 v = make_float2(0.f, 0.f);
        if (valid) v = base[(size_t)zz*65536 + xl];
        sl[drev4(zz)]       = v;
        sl[drev4(zz + 128)] = make_float2(0.f, 0.f);
    }
    fft256_r4s<-1,16,3>(sl, u);
    if (valid){
#pragma unroll
        for (int k = 0; k < 4; ++k){
            int j = (k << 4) + u;
            float2 o0,o1,o2,o3;
            fft256_last<-1>(sl, j, o0,o1,o2,o3);
            base[(size_t)j*65536 + xl]         = o0;
            base[(size_t)(j + 64)*65536 + xl]  = o1;
            base[(size_t)(j + 128)*65536 + xl] = o2;
            base[(size_t)(j + 192)*65536 + xl] = o3;
        }
    }
}

// 0.5 * x-stencil for one staged source row. rd = direct row (plane izu),
// rc = conj row (plane izn, mirrored y); conj applied to rc values here.
__device__ __forceinline__ float2 avg_row(const float2* rd, const float2* rc, int jx){
    if (jx == 0){
        float2 a = rc[1], b = rd[0];
        return make_float2(0.5f*(a.x + b.x), 0.5f*(b.y - a.y));
    } else if (jx <= 127){
        float2 a = rd[jx-1], b = rd[jx];
        return make_float2(0.5f*(a.x + b.x), 0.5f*(a.y + b.y));
    } else if (jx == 128){
        float2 b = rd[128];
        return make_float2(0.5f*b.x, 0.5f*b.y);
    } else if (jx == 129){
        float2 a = rd[128], b = rc[127];
        return make_float2(0.5f*(a.x + b.x), 0.5f*(a.y - b.y));
    } else {
        float2 a = rc[256-jx], b = rc[257-jx];
        return make_float2(0.5f*(a.x + b.x), -0.5f*(a.y + b.y));
    }
}

// 2x2 x/y average with Hermitian conj reconstruction, shared-row staged.
// Block: 4 consecutive jy x one z-plane; stages 5 direct + 5 conj rows.
__global__ void k_avg(){
    __shared__ float2 rd[5][132];
    __shared__ float2 rc[5][132];
    int tid = threadIdx.x;
    int jy0 = blockIdx.x << 2;
    int izu = blockIdx.y, b = blockIdx.z;
    int sy0 = jy0 ^ 128;                 // 4-aligned tiles never straddle 128
    int izn = (256 - izu) & 255;
    const float2* Ab = g_A + ((size_t)b << 24);
    {
        int half = tid >> 7;             // 0: direct rows, 1: conj rows
        int xt = tid & 127;
#pragma unroll
        for (int r = 0; r < 5; ++r){
            int iy = sy0 - 1 + r;        // -1 only when sy0 == 0
            int iyu = (iy >= 0) ? (iy ^ 128) : 0;
            int row = half ? ((256 - iyu) & 255) : iyu;
            int pl  = half ? izn : izu;
            const float2* src = Ab + ((size_t)pl << 16) + ((size_t)row << 8);
#pragma unroll
            for (int x = xt; x < 129; x += 128){
                float2 v = make_float2(0.f, 0.f);
                if (iy >= 0) v = __ldg(&src[x]);
                if (half) rc[r][x] = v; else rd[r][x] = v;
            }
        }
    }
    __syncthreads();
    int q = tid & 127;                   // jx pair index
    int jl = tid >> 7;
    int jx0 = q << 1;
#pragma unroll
    for (int dj = 0; dj < 2; ++dj){
        int k = (jl << 1) + dj;          // local jy in [0,4)
        int jy = jy0 + k;
        const float2* rd0 = rd[k];   const float2* rc0 = rc[k];
        const float2* rd1 = rd[k+1]; const float2* rc1 = rc[k+1];
        float2 vA0 = avg_row(rd0, rc0, jx0);
        float2 vB0 = avg_row(rd1, rc1, jx0);
        float2 vA1 = avg_row(rd0, rc0, jx0+1);
        float2 vB1 = avg_row(rd1, rc1, jx0+1);
        float4 o;
        o.x = 0.5f*(vA0.x + vB0.x);  o.y = 0.5f*(vA0.y + vB0.y);
        o.z = 0.5f*(vA1.x + vB1.x);  o.w = 0.5f*(vA1.y + vB1.y);
        *(float4*)&g_C[((size_t)b << 23) + ((size_t)izu << 16) + ((size_t)jy << 8) + (size_t)jx0] = o;
    }
}

// Fused Stolt z-interp + inverse X FFT. 2 coalesced loads per sample from g_C.
// Block: 4 jy-lines x 64 threads; jz slabbed via jz0.
__global__ void k_resample_invx(int jz0){
    __shared__ float2 s[4*256];
    int tid = threadIdx.x;
    int line = tid >> 6, t = tid & 63;
    int jy = (blockIdx.x << 2) + line;
    int jz = jz0 + blockIdx.y;      // in [1,128)
    int b  = blockIdx.z;
    int sy = jy ^ 128;
    float gz = (float)jz * (1.0f/128.0f);
    float gy = (float)(sy - 128) * (1.0f/128.0f);
    const float fk = 0.1024f;
    float gyz = fk*gy*gy + gz*gz;
    const float2* Cb = g_C + ((size_t)b << 23) + ((size_t)jy << 8);
    float2* sl = s + (line << 8);
#pragma unroll
    for (int k = 0; k < 4; ++k){
        int jx = t + (k << 6);
        int sx = jx ^ 128;
        float gx = (float)(sx - 128) * (1.0f/128.0f);
        float gznew = sqrtf(fk*gx*gx + gyz);
        float pz = (gznew + 1.0f)*128.0f - 0.5f;    // >= 128.5
        float z0f = floorf(pz);
        float dz = pz - z0f;
        int z0u = (int)z0f - 128;                   // >= 0
        float2 c0 = make_float2(0.f, 0.f), c1 = make_float2(0.f, 0.f);
        if (z0u <= 127) c0 = __ldg(&Cb[((size_t)z0u << 16) + (size_t)jx]);
        if (z0u <= 126) c1 = __ldg(&Cb[((size_t)(z0u + 1) << 16) + (size_t)jx]);
        float w0 = 1.0f - dz;
        float fac = gz / (gznew + 1e-8f) * (1.0f/256.0f);
        sl[drev4(jx)] = make_float2((w0*c0.x + dz*c1.x) * fac,
                                    (w0*c0.y + dz*c1.y) * fac);
    }
    fft256_r4s<1,64,3>(sl, t);
    float2 o0,o1,o2,o3;
    fft256_last<1>(sl, t, o0,o1,o2,o3);
    size_t o = ((size_t)b << 24) + ((size_t)jz << 16) + ((size_t)jy << 8);
    g_B[o + t]      = o0;
    g_B[o + t + 64] = o1;
}

// Inverse Y: lines (b, jz slab, x<128). Read all y, write y<128 (scaled).
__global__ void k_inv_y(int jz0){
    __shared__ float2 s[16*257];
    int x0 = blockIdx.x << 4, zz = jz0 + blockIdx.y, b = blockIdx.z;
    int tid = threadIdx.x, xl = tid & 15, u = tid >> 4;
    float2* base = g_B + ((size_t)b << 24) + ((size_t)zz << 16) + x0;
    float2* sl = s + xl*257;
#pragma unroll
    for (int c = 0; c < 16; ++c){
        int yy = (c << 4) + u;
        sl[drev4(yy)] = base[(size_t)yy*256 + xl];
    }
    fft256_r4s<1,16,3>(sl, u);
#pragma unroll
    for (int k = 0; k < 4; ++k){
        int j = (k << 4) + u;               // < 64
        float2 o0,o1,o2,o3;
        fft256_last<1>(sl, j, o0,o1,o2,o3);
        base[(size_t)j*256 + xl]        = make_float2(o0.x*(1.f/256.f), o0.y*(1.f/256.f));
        base[(size_t)(j + 64)*256 + xl] = make_float2(o1.x*(1.f/256.f), o1.y*(1.f/256.f));
    }
}

// Inverse Z: lines (b, y<128, x<128). Only z in [1,128) nonzero.
__global__ void k_inv_z(float* __restrict__ out){
    __shared__ float2 s[16*257];
    int x0 = blockIdx.x << 4, y = blockIdx.y, b = blockIdx.z;
    int tid = threadIdx.x, xl = tid & 15, u = tid >> 4;
    const float2* base = g_B + ((size_t)b << 24) + ((size_t)y << 8) + x0;
    float2* sl = s + xl*257;
#pragma unroll
    for (int c = 0; c < 8; ++c){
        int zz = (c << 4) + u;                  // 0..127
        float2 v = make_float2(0.f, 0.f);
        if (zz >= 1) v = base[(size_t)zz*65536 + xl];
        sl[drev4(zz)]       = v;
        sl[drev4(zz + 128)] = make_float2(0.f, 0.f);
    }
    fft256_r4s<1,16,3>(sl, u);
    float* outb = out + ((size_t)b*128*128*128) + (size_t)y*128 + (size_t)(x0 + xl);
#pragma unroll
    for (int k = 0; k < 4; ++k){
        int j = (k << 4) + u;               // < 64
        float2 o0,o1,o2,o3;
        fft256_last<1>(sl, j, o0,o1,o2,o3);
        outb[(size_t)j*16384]        = o0.x * (1.f/256.f);
        outb[(size_t)(j + 64)*16384] = o1.x * (1.f/256.f);
    }
}

extern "C" void kernel_launch(void* const* d_in, const int* in_sizes, int n_in,
                              void* d_out, int out_size){
    (void)in_sizes; (void)n_in; (void)out_size;
    const float* in = (const float*)d_in[0];
    float* out = (float*)d_out;

    k_fwd_x<<<dim3(32, 128, 2), 256>>>(in);
    k_fwd_y<<<dim3(9,  128, 2), 256>>>();
    k_fwd_z<<<dim3(9,  256, 2), 256>>>();
    k_avg  <<<dim3(64, 128, 2), 256>>>();

    // jz-slab pairing: resample writes a 16.8 MB slab, inv_y reads it from L2.
    const int starts[4] = {1, 33, 65, 97};
    const int counts[4] = {32, 32, 32, 31};
    for (int s = 0; s < 4; ++s){
        k_resample_invx<<<dim3(64, counts[s], 2), 256>>>(starts[s]);
        k_inv_y        <<<dim3(8,  counts[s], 2), 256>>>(starts[s]);
    }
    k_inv_z<<<dim3(8, 128, 2), 256>>>(out);
}

// round 6
// speedup vs baseline: 1.2785x; 1.2785x over previous
#include <cuda_runtime.h>
#include <cstdint>

#define PI_F 3.14159265358979323846f
static __device__ float2 g_A[33554432];   // stenciled forward spectrum, cols m<=129 valid
static __device__ float2 g_B[33554432];   // inverse pipeline
static __device__ float2 g_E[131072];     // [b][z][m]: y-stencil "full" value at jy=128

__device__ __forceinline__ float2 cmul(float2 a, float2 b){
    return make_float2(a.x*b.x - a.y*b.y, a.x*b.y + a.y*b.x);
}
// base-4 digit reversal of an 8-bit index
__device__ __forceinline__ int drev4(int i){
    return ((i & 3) << 6) | (((i >> 2) & 3) << 4) | (((i >> 4) & 3) << 2) | ((i >> 6) & 3);
}

// First NSTAGES stages of a 256-pt radix-4 DIT FFT in shared (drev4-ordered
// input; natural output after 4 stages). NT threads per line.
template<int SIGN, int NT, int NSTAGES>
__device__ __forceinline__ void fft256_r4s(float2* s, int t){
#pragma unroll
    for (int st = 0; st < NSTAGES; ++st){
        int L = 1 << (2*st);
        __syncthreads();
#pragma unroll
        for (int k = 0; k < 64/NT; ++k){
            int j = t + k*NT;
            int p = j & (L - 1);
            int base = ((j >> (2*st)) << (2*st + 2)) + p;
            float ang = (float)SIGN * (2.0f*PI_F) * (float)p / (float)(4*L);
            float sn, cs; __sincosf(ang, &sn, &cs);
            float2 w1 = make_float2(cs, sn);
            float2 w2 = make_float2(cs*cs - sn*sn, 2.0f*cs*sn);
            float2 w3 = cmul(w1, w2);
            float2 a0 = s[base];
            float2 a1 = cmul(w1, s[base + L]);
            float2 a2 = cmul(w2, s[base + 2*L]);
            float2 a3 = cmul(w3, s[base + 3*L]);
            float2 t02p = make_float2(a0.x + a2.x, a0.y + a2.y);
            float2 t02m = make_float2(a0.x - a2.x, a0.y - a2.y);
            float2 t13p = make_float2(a1.x + a3.x, a1.y + a3.y);
            float2 t13m = make_float2(a1.x - a3.x, a1.y - a3.y);
            float2 jt = (SIGN < 0) ? make_float2(t13m.y, -t13m.x)
                                   : make_float2(-t13m.y, t13m.x);
            s[base]       = make_float2(t02p.x + t13p.x, t02p.y + t13p.y);
            s[base + L]   = make_float2(t02m.x + jt.x,   t02m.y + jt.y);
            s[base + 2*L] = make_float2(t02p.x - t13p.x, t02p.y - t13p.y);
            s[base + 3*L] = make_float2(t02m.x - jt.x,   t02m.y - jt.y);
        }
    }
    __syncthreads();
}

// Last stage (L=64) in registers from shared. Butterfly j in [0,64).
template<int SIGN>
__device__ __forceinline__ void fft256_last(const float2* s, int j,
        float2& o0, float2& o1, float2& o2, float2& o3){
    float ang = (float)SIGN * (2.0f*PI_F) * (float)j * (1.0f/256.0f);
    float sn, cs; __sincosf(ang, &sn, &cs);
    float2 w1 = make_float2(cs, sn);
    float2 w2 = make_float2(cs*cs - sn*sn, 2.0f*cs*sn);
    float2 w3 = cmul(w1, w2);
    float2 a0 = s[j];
    float2 a1 = cmul(w1, s[j + 64]);
    float2 a2 = cmul(w2, s[j + 128]);
    float2 a3 = cmul(w3, s[j + 192]);
    float2 t02p = make_float2(a0.x + a2.x, a0.y + a2.y);
    float2 t02m = make_float2(a0.x - a2.x, a0.y - a2.y);
    float2 t13p = make_float2(a1.x + a3.x, a1.y + a3.y);
    float2 t13m = make_float2(a1.x - a3.x, a1.y - a3.y);
    float2 jt = (SIGN < 0) ? make_float2(t13m.y, -t13m.x)
                           : make_float2(-t13m.y, t13m.x);
    o0 = make_float2(t02p.x + t13p.x, t02p.y + t13p.y);
    o1 = make_float2(t02m.x + jt.x,   t02m.y + jt.y);
    o2 = make_float2(t02p.x - t13p.x, t02p.y - t13p.y);
    o3 = make_float2(t02m.x - jt.x,   t02m.y - jt.y);
}

// Forward X + prep + X-STENCIL epilogue.
// Stored cols: m in [0,127]: Dv[m]=0.5(X[(m-1)&255]+X[m]);
//              m=128: 0.5*X[128] (sx=0 drop exception); m=129: 0.5(X[127]+X[128]).
// Block: 4 lines x 64 threads.
__global__ void k_fwd_x(const float* __restrict__ in){
    __shared__ float2 s[4*256];
    int tid = threadIdx.x;
    int l = tid >> 6, t = tid & 63;
    int y = (blockIdx.x << 2) + l;
    int zz = blockIdx.y, b = blockIdx.z;
    float g = (float)zz * (1.0f/127.0f);
    float g2 = g*g;
    const float* row = in + (((size_t)b*128 + zz)*128 + y)*128;
    float2* sl = s + (l << 8);
#pragma unroll
    for (int k = 0; k < 4; ++k){
        int j = t + (k << 6);
        int src = drev4(j);
        float v = 0.0f;
        if (src < 128) v = sqrtf(fmaxf(row[src]*g2, 0.0f));
        sl[j] = make_float2(v, 0.0f);
    }
    fft256_r4s<-1,64,4>(sl, t);
    float2* outl = g_A + (((size_t)b*256 + zz)*256 + y)*256;
#pragma unroll
    for (int h = 0; h < 2; ++h){
        int m = t + (h << 6);           // 0..127
        float2 a = sl[(m - 1) & 255];
        float2 c = sl[m];
        outl[m] = make_float2(0.5f*(a.x + c.x), 0.5f*(a.y + c.y));
    }
    if (t == 0){
        float2 c = sl[128];
        outl[128] = make_float2(0.5f*c.x, 0.5f*c.y);
    } else if (t == 1){
        float2 a = sl[127], c = sl[128];
        outl[129] = make_float2(0.5f*(a.x + c.x), 0.5f*(a.y + c.y));
    }
}

// Forward Y + Y-STENCIL epilogue, x cols [0,129]. Read y<128 (zero-pad).
// Row jy (!=128): 0.5(Y[(jy-1)&255]+Y[jy]); jy=128: 0.5*Y[128] (exception).
// Extra: g_E[b][z][m] = 0.5(Y[127]+Y[128]) (full value for conj mirror at jy=129).
__global__ void k_fwd_y(){
    __shared__ float2 s[16*257];
    int x0 = blockIdx.x << 4, zz = blockIdx.y, b = blockIdx.z;
    int tid = threadIdx.x, xl = tid & 15, u = tid >> 4;
    bool valid = (x0 + xl) <= 129;
    float2* base = g_A + ((size_t)b << 24) + ((size_t)zz << 16) + x0;
    float2* sl = s + xl*257;
#pragma unroll
    for (int c = 0; c < 8; ++c){
        int yy = (c << 4) + u;
        float2 v = make_float2(0.f, 0.f);
        if (valid) v = base[(size_t)yy*256 + xl];
        sl[drev4(yy)]       = v;
        sl[drev4(yy + 128)] = make_float2(0.f, 0.f);
    }
    fft256_r4s<-1,16,4>(sl, u);
    if (valid){
#pragma unroll
        for (int c = 0; c < 16; ++c){
            int jy = (c << 4) + u;
            float2 v;
            if (jy == 128){
                float2 cc = sl[128];
                v = make_float2(0.5f*cc.x, 0.5f*cc.y);
            } else {
                float2 a = sl[(jy - 1) & 255];
                float2 cc = sl[jy];
                v = make_float2(0.5f*(a.x + cc.x), 0.5f*(a.y + cc.y));
            }
            base[(size_t)jy*256 + xl] = v;
        }
        if (u == 0){
            float2 a = sl[127], cc = sl[128];
            g_E[((size_t)b << 16) + ((size_t)zz << 8) + (size_t)(x0 + xl)]
                = make_float2(0.5f*(a.x + cc.x), 0.5f*(a.y + cc.y));
        }
    }
}

// Forward Z: x cols [0,129]. Read z<128 (zero-pad), write all 256 z.
__global__ void k_fwd_z(){
    __shared__ float2 s[16*257];
    int x0 = blockIdx.x << 4, y = blockIdx.y, b = blockIdx.z;
    int tid = threadIdx.x, xl = tid & 15, u = tid >> 4;
    bool valid = (x0 + xl) <= 129;
    float2* base = g_A + ((size_t)b << 24) + ((size_t)y << 8) + x0;
    float2* sl = s + xl*257;
#pragma unroll
    for (int c = 0; c < 8; ++c){
        int zz = (c << 4) + u;
        float2 v = make_float2(0.f, 0.f);
        if (valid) v = base[(size_t)zz*65536 + xl];
        sl[drev4(zz)]       = v;
        sl[drev4(zz + 128)] = make_float2(0.f, 0.f);
    }
    fft256_r4s<-1,16,3>(sl, u);
    if (valid){
#pragma unroll
        for (int k = 0; k < 4; ++k){
            int j = (k << 4) + u;
            float2 o0,o1,o2,o3;
            fft256_last<-1>(sl, j, o0,o1,o2,o3);
            base[(size_t)j*65536 + xl]         = o0;
            base[(size_t)(j + 64)*65536 + xl]  = o1;
            base[(size_t)(j + 128)*65536 + xl] = o2;
            base[(size_t)(j + 192)*65536 + xl] = o3;
        }
    }
}

// Forward Z over the g_E side buffer: lines along z (stride 256) per m-col.
__global__ void k_fwd_z_e(){
    __shared__ float2 s[16*257];
    int x0 = blockIdx.x << 4, b = blockIdx.z;
    int tid = threadIdx.x, xl = tid & 15, u = tid >> 4;
    bool valid = (x0 + xl) <= 129;
    float2* base = g_E + ((size_t)b << 16) + x0;
    float2* sl = s + xl*257;
#pragma unroll
    for (int c = 0; c < 8; ++c){
        int zz = (c << 4) + u;
        float2 v = make_float2(0.f, 0.f);
        if (valid) v = base[(size_t)zz*256 + xl];
        sl[drev4(zz)]       = v;
        sl[drev4(zz + 128)] = make_float2(0.f, 0.f);
    }
    fft256_r4s<-1,16,3>(sl, u);
    if (valid){
#pragma unroll
        for (int k = 0; k < 4; ++k){
            int j = (k << 4) + u;
            float2 o0,o1,o2,o3;
            fft256_last<-1>(sl, j, o0,o1,o2,o3);
            base[(size_t)j*256 + xl]         = o0;
            base[(size_t)(j + 64)*256 + xl]  = o1;
            base[(size_t)(j + 128)*256 + xl] = o2;
            base[(size_t)(j + 192)*256 + xl] = o3;
        }
    }
}

// Fused Stolt z-interp + inverse X FFT. 2 loads per sample directly from the
// stenciled spectrum (direct region) or its 3D conj mirror (jx>=129).
// Block: 4 jy-lines x 64 threads; each thread 4 jx samples.
__global__ void k_resample_invx(){
    __shared__ float2 s[4*256];
    int tid = threadIdx.x;
    int line = tid >> 6, t = tid & 63;
    int jy = (blockIdx.x << 2) + line;
    int jz = blockIdx.y + 1;        // 1..127
    int b  = blockIdx.z;
    int sy = jy ^ 128;
    float gz = (float)jz * (1.0f/128.0f);
    float gy = (float)(sy - 128) * (1.0f/128.0f);
    const float fk = 0.1024f;
    float gyz = fk*gy*gy + gz*gz;
    const float2* Ab = g_A + ((size_t)b << 24);
    const float2* Eb = g_E + ((size_t)b << 16);
    float2* sl = s + (line << 8);
    // conj-region row: jy==128 -> exception slot 128; jy==129 -> g_E; else (257-jy)&255
    int ry = (jy == 128) ? 128 : ((257 - jy) & 255);
    bool useE = (jy == 129);
#pragma unroll
    for (int k = 0; k < 4; ++k){
        int jx = t + (k << 6);
        int sx = jx ^ 128;
        float gx = (float)(sx - 128) * (1.0f/128.0f);
        float gznew = sqrtf(fk*gx*gx + gyz);
        float pz = (gznew + 1.0f)*128.0f - 0.5f;    // >= 128.5
        float z0f = floorf(pz);
        float dz = pz - z0f;
        int z0u = (int)z0f - 128;                   // >= 0
        float accx = 0.f, accy = 0.f;
#pragma unroll
        for (int tz = 0; tz < 2; ++tz){
            int zp = z0u + tz;
            if (zp > 127) continue;
            float w = tz ? dz : (1.0f - dz);
            float2 v;
            if (jx <= 128){
                v = __ldg(&Ab[((size_t)zp << 16) + ((size_t)jy << 8) + (size_t)jx]);
            } else {
                int m = (jx == 129) ? 129 : (257 - jx);
                int zq = (256 - zp) & 255;
                if (useE){
                    float2 e = __ldg(&Eb[((size_t)zq << 8) + (size_t)m]);
                    v = make_float2(e.x, -e.y);
                } else {
                    float2 e = __ldg(&Ab[((size_t)zq << 16) + ((size_t)ry << 8) + (size_t)m]);
                    v = make_float2(e.x, -e.y);
                }
            }
            accx += w * v.x; accy += w * v.y;
        }
        float fac = gz / (gznew + 1e-8f) * (1.0f/256.0f);
        sl[drev4(jx)] = make_float2(accx * fac, accy * fac);
    }
    fft256_r4s<1,64,3>(sl, t);
    float2 o0,o1,o2,o3;
    fft256_last<1>(sl, t, o0,o1,o2,o3);
    size_t o = ((size_t)b << 24) + ((size_t)jz << 16) + ((size_t)jy << 8);
    g_B[o + t]      = o0;
    g_B[o + t + 64] = o1;
}

// Inverse Y: lines (b, z in [1,128), x<128). Read all y, write y<128 (scaled).
__global__ void k_inv_y(){
    __shared__ float2 s[16*257];
    int x0 = blockIdx.x << 4, zz = blockIdx.y + 1, b = blockIdx.z;
    int tid = threadIdx.x, xl = tid & 15, u = tid >> 4;
    float2* base = g_B + ((size_t)b << 24) + ((size_t)zz << 16) + x0;
    float2* sl = s + xl*257;
#pragma unroll
    for (int c = 0; c < 16; ++c){
        int yy = (c << 4) + u;
        sl[drev4(yy)] = base[(size_t)yy*256 + xl];
    }
    fft256_r4s<1,16,3>(sl, u);
#pragma unroll
    for (int k = 0; k < 4; ++k){
        int j = (k << 4) + u;               // < 64
        float2 o0,o1,o2,o3;
        fft256_last<1>(sl, j, o0,o1,o2,o3);
        base[(size_t)j*256 + xl]        = make_float2(o0.x*(1.f/256.f), o0.y*(1.f/256.f));
        base[(size_t)(j + 64)*256 + xl] = make_float2(o1.x*(1.f/256.f), o1.y*(1.f/256.f));
    }
}

// Inverse Z: lines (b, y<128, x<128). Only z in [1,128) nonzero.
__global__ void k_inv_z(float* __restrict__ out){
    __shared__ float2 s[16*257];
    int x0 = blockIdx.x << 4, y = blockIdx.y, b = blockIdx.z;
    int tid = threadIdx.x, xl = tid & 15, u = tid >> 4;
    const float2* base = g_B + ((size_t)b << 24) + ((size_t)y << 8) + x0;
    float2* sl = s + xl*257;
#pragma unroll
    for (int c = 0; c < 8; ++c){
        int zz = (c << 4) + u;                  // 0..127
        float2 v = make_float2(0.f, 0.f);
        if (zz >= 1) v = base[(size_t)zz*65536 + xl];
        sl[drev4(zz)]       = v;
        sl[drev4(zz + 128)] = make_float2(0.f, 0.f);
    }
    fft256_r4s<1,16,3>(sl, u);
    float* outb = out + ((size_t)b*128*128*128) + (size_t)y*128 + (size_t)(x0 + xl);
#pragma unroll
    for (int k = 0; k < 4; ++k){
        int j = (k << 4) + u;               // < 64
        float2 o0,o1,o2,o3;
        fft256_last<1>(sl, j, o0,o1,o2,o3);
        outb[(size_t)j*16384]        = o0.x * (1.f/256.f);
        outb[(size_t)(j + 64)*16384] = o1.x * (1.f/256.f);
    }
}

extern "C" void kernel_launch(void* const* d_in, const int* in_sizes, int n_in,
                              void* d_out, int out_size){
    (void)in_sizes; (void)n_in; (void)out_size;
    const float* in = (const float*)d_in[0];
    float* out = (float*)d_out;

    k_fwd_x        <<<dim3(32, 128, 2), 256>>>(in);
    k_fwd_y        <<<dim3(9,  128, 2), 256>>>();
    k_fwd_z        <<<dim3(9,  256, 2), 256>>>();
    k_fwd_z_e      <<<dim3(9,  1,   2), 256>>>();
    k_resample_invx<<<dim3(64, 127, 2), 256>>>();
    k_inv_y        <<<dim3(8,  127, 2), 256>>>();
    k_inv_z        <<<dim3(8,  128, 2), 256>>>(out);
}

// round 12
// speedup vs baseline: 1.5829x; 1.2381x over previous
#include <cuda_runtime.h>
#include <cstdint>

#define PI_F 3.14159265358979323846f
static __device__ __align__(16) float2 g_A[33554432];  // stenciled fwd spectrum, cols m<=129
static __device__ __align__(16) float2 g_B[33554432];  // inverse pipeline
static __device__ __align__(16) float2 g_E[131072];    // [b][z][m]: y-stencil full value @ jy=128

__device__ __forceinline__ float2 cmul(float2 a, float2 b){
    return make_float2(a.x*b.x - a.y*b.y, a.x*b.y + a.y*b.x);
}
// 3-digit base-4 reversal (quads); involution.
__device__ __forceinline__ int dr3(int q){
    return ((q & 3) << 4) | (((q >> 2) & 3) << 2) | ((q >> 4) & 3);
}
// skewed shared index: breaks 64-stride bank alignment
__device__ __forceinline__ int sidx(int p){ return p + (p >> 6); }

// Radix-4 stage 0 from registers (natural inputs n0, n0+64, n0+128, n0+192),
// results to shared quad q (positions 4q..4q+3), skew-indexed.
template<int SIGN>
__device__ __forceinline__ void stage0_reg(float2 a0, float2 a1, float2 a2, float2 a3,
                                           float2* s, int q){
    float2 t02p = make_float2(a0.x + a2.x, a0.y + a2.y);
    float2 t02m = make_float2(a0.x - a2.x, a0.y - a2.y);
    float2 t13p = make_float2(a1.x + a3.x, a1.y + a3.y);
    float2 t13m = make_float2(a1.x - a3.x, a1.y - a3.y);
    float2 jt = (SIGN < 0) ? make_float2(t13m.y, -t13m.x)
                           : make_float2(-t13m.y, t13m.x);
    int b4 = 4*q;
    s[sidx(b4)]   = make_float2(t02p.x + t13p.x, t02p.y + t13p.y);
    s[sidx(b4+1)] = make_float2(t02m.x + jt.x,   t02m.y + jt.y);
    s[sidx(b4+2)] = make_float2(t02p.x - t13p.x, t02p.y - t13p.y);
    s[sidx(b4+3)] = make_float2(t02m.x - jt.x,   t02m.y - jt.y);
}

// One radix-4 butterfly of stage st (>=1) at logical index j, skew-indexed shared.
template<int SIGN>
__device__ __forceinline__ void bfly_r4(float2* s, int j, int st){
    int L = 1 << (2*st);
    int p = j & (L - 1);
    int base = ((j >> (2*st)) << (2*st + 2)) + p;
    float ang = (float)SIGN * (2.0f*PI_F) * (float)p / (float)(4*L);
    float sn, cs; __sincosf(ang, &sn, &cs);
    float2 w1 = make_float2(cs, sn);
    float2 w2 = make_float2(cs*cs - sn*sn, 2.0f*cs*sn);
    float2 w3 = cmul(w1, w2);
    int i0 = sidx(base), i1 = sidx(base+L), i2 = sidx(base+2*L), i3 = sidx(base+3*L);
    float2 a0 = s[i0];
    float2 a1 = cmul(w1, s[i1]);
    float2 a2 = cmul(w2, s[i2]);
    float2 a3 = cmul(w3, s[i3]);
    float2 t02p = make_float2(a0.x + a2.x, a0.y + a2.y);
    float2 t02m = make_float2(a0.x - a2.x, a0.y - a2.y);
    float2 t13p = make_float2(a1.x + a3.x, a1.y + a3.y);
    float2 t13m = make_float2(a1.x - a3.x, a1.y - a3.y);
    float2 jt = (SIGN < 0) ? make_float2(t13m.y, -t13m.x)
                           : make_float2(-t13m.y, t13m.x);
    s[i0] = make_float2(t02p.x + t13p.x, t02p.y + t13p.y);
    s[i1] = make_float2(t02m.x + jt.x,   t02m.y + jt.y);
    s[i2] = make_float2(t02p.x - t13p.x, t02p.y - t13p.y);
    s[i3] = make_float2(t02m.x - jt.x,   t02m.y - jt.y);
}

// Stages [1, NSTAGES) on one shared line, NT threads.
template<int SIGN, int NT, int NSTAGES>
__device__ __forceinline__ void fft_mid(float2* s, int t){
#pragma unroll
    for (int st = 1; st < NSTAGES; ++st){
        __syncthreads();
#pragma unroll
        for (int k = 0; k < 64/NT; ++k) bfly_r4<SIGN>(s, t + k*NT, st);
    }
    __syncthreads();
}

// Stages [1, NSTAGES) on a pair of shared lines, 32 threads per line-pair.
template<int SIGN, int NSTAGES>
__device__ __forceinline__ void fft_mid_x2(float2* sa, float2* sb, int u){
#pragma unroll
    for (int st = 1; st < NSTAGES; ++st){
        __syncthreads();
#pragma unroll
        for (int k = 0; k < 2; ++k){
            int j = u + (k << 5);
            bfly_r4<SIGN>(sa, j, st);
            bfly_r4<SIGN>(sb, j, st);
        }
    }
    __syncthreads();
}

// Last stage (L=64) in registers from (skewed) shared. Butterfly j in [0,64).
template<int SIGN>
__device__ __forceinline__ void fft256_last(const float2* s, int j,
        float2& o0, float2& o1, float2& o2, float2& o3){
    float ang = (float)SIGN * (2.0f*PI_F) * (float)j * (1.0f/256.0f);
    float sn, cs; __sincosf(ang, &sn, &cs);
    float2 w1 = make_float2(cs, sn);
    float2 w2 = make_float2(cs*cs - sn*sn, 2.0f*cs*sn);
    float2 w3 = cmul(w1, w2);
    float2 a0 = s[sidx(j)];
    float2 a1 = cmul(w1, s[sidx(j + 64)]);
    float2 a2 = cmul(w2, s[sidx(j + 128)]);
    float2 a3 = cmul(w3, s[sidx(j + 192)]);
    float2 t02p = make_float2(a0.x + a2.x, a0.y + a2.y);
    float2 t02m = make_float2(a0.x - a2.x, a0.y - a2.y);
    float2 t13p = make_float2(a1.x + a3.x, a1.y + a3.y);
    float2 t13m = make_float2(a1.x - a3.x, a1.y - a3.y);
    float2 jt = (SIGN < 0) ? make_float2(t13m.y, -t13m.x)
                           : make_float2(-t13m.y, t13m.x);
    o0 = make_float2(t02p.x + t13p.x, t02p.y + t13p.y);
    o1 = make_float2(t02m.x + jt.x,   t02m.y + jt.y);
    o2 = make_float2(t02p.x - t13p.x, t02p.y - t13p.y);
    o3 = make_float2(t02m.x - jt.x,   t02m.y - jt.y);
}

// Forward X + prep + X-STENCIL epilogue. Block: 4 lines x 64 threads.
__global__ void k_fwd_x(const float* __restrict__ in){
    __shared__ float2 s[4*260];
    int tid = threadIdx.x;
    int l = tid >> 6, t = tid & 63;
    int y = (blockIdx.x << 2) + l;
    int zz = blockIdx.y, bb = blockIdx.z;
    float g = (float)zz * (1.0f/127.0f);
    float g2 = g*g;
    const float* row = in + (((size_t)bb*128 + zz)*128 + y)*128;
    float2* sl = s + l*260;
    {
        float v0 = sqrtf(fmaxf(row[t]*g2, 0.0f));
        float v1 = sqrtf(fmaxf(row[t + 64]*g2, 0.0f));
        float2 z2 = make_float2(0.f, 0.f);
        stage0_reg<-1>(make_float2(v0, 0.f), make_float2(v1, 0.f), z2, z2, sl, dr3(t));
    }
    fft_mid<-1,64,4>(sl, t);
    float2* outl = g_A + (((size_t)bb*256 + zz)*256 + y)*256;
#pragma unroll
    for (int h = 0; h < 2; ++h){
        int m = t + (h << 6);
        float2 a = sl[sidx((m - 1) & 255)];
        float2 c = sl[sidx(m)];
        outl[m] = make_float2(0.5f*(a.x + c.x), 0.5f*(a.y + c.y));
    }
    if (t == 0){
        float2 c = sl[sidx(128)];
        outl[128] = make_float2(0.5f*c.x, 0.5f*c.y);
    } else if (t == 1){
        float2 a = sl[sidx(127)], c = sl[sidx(128)];
        outl[129] = make_float2(0.5f*(a.x + c.x), 0.5f*(a.y + c.y));
    }
}

// Forward Y + Y-STENCIL epilogue. Column-pair layout: 8 pairs x 32 threads.
// Row stride of g_A in float4 units = 128.
__global__ void k_fwd_y(){
    __shared__ float2 s[16*261];
    int x0 = blockIdx.x << 4, zz = blockIdx.y, bb = blockIdx.z;
    int tid = threadIdx.x, xp = tid & 7, u = tid >> 3;
    bool valid = (x0 + 2*xp) <= 128;
    float2* base = g_A + ((size_t)bb << 24) + ((size_t)zz << 16) + x0;
    float4* base4 = (float4*)base;
    float2* sl0 = s + (2*xp)*261;
    float2* sl1 = sl0 + 261;
#pragma unroll
    for (int c = 0; c < 2; ++c){
        int q = (c << 5) + u;
        int n0 = dr3(q);                  // < 64; rows n0, n0+64 are the data
        float4 v0 = make_float4(0.f,0.f,0.f,0.f), v1 = v0;
        if (valid){
            v0 = base4[(size_t)n0*128 + xp];
            v1 = base4[(size_t)(n0 + 64)*128 + xp];
        }
        float2 z2 = make_float2(0.f, 0.f);
        stage0_reg<-1>(make_float2(v0.x,v0.y), make_float2(v1.x,v1.y), z2, z2, sl0, q);
        stage0_reg<-1>(make_float2(v0.z,v0.w), make_float2(v1.z,v1.w), z2, z2, sl1, q);
    }
    fft_mid_x2<-1,4>(sl0, sl1, u);
    if (valid){
#pragma unroll
        for (int c = 0; c < 8; ++c){
            int jy = (c << 5) + u;
            float2 v0, v1;
            if (jy == 128){
                float2 c0 = sl0[sidx(128)], c1 = sl1[sidx(128)];
                v0 = make_float2(0.5f*c0.x, 0.5f*c0.y);
                v1 = make_float2(0.5f*c1.x, 0.5f*c1.y);
            } else {
                int jm = (jy - 1) & 255;
                float2 a0 = sl0[sidx(jm)], c0 = sl0[sidx(jy)];
                float2 a1 = sl1[sidx(jm)], c1 = sl1[sidx(jy)];
                v0 = make_float2(0.5f*(a0.x + c0.x), 0.5f*(a0.y + c0.y));
                v1 = make_float2(0.5f*(a1.x + c1.x), 0.5f*(a1.y + c1.y));
            }
            base4[(size_t)jy*128 + xp] = make_float4(v0.x, v0.y, v1.x, v1.y);
        }
        if (u == 0){
            float2 a0 = sl0[sidx(127)], c0 = sl0[sidx(128)];
            float2 a1 = sl1[sidx(127)], c1 = sl1[sidx(128)];
            float4* E4 = (float4*)(g_E + ((size_t)bb << 16) + ((size_t)zz << 8) + x0);
            E4[xp] = make_float4(0.5f*(a0.x + c0.x), 0.5f*(a0.y + c0.y),
                                 0.5f*(a1.x + c1.x), 0.5f*(a1.y + c1.y));
        }
    }
}

// Forward Z (merged: blockIdx.y==256 handles the g_E side buffer).
__global__ void k_fwd_z(){
    __shared__ float2 s[16*261];
    int x0 = blockIdx.x << 4, y = blockIdx.y, bb = blockIdx.z;
    int tid = threadIdx.x, xp = tid & 7, u = tid >> 3;
    bool valid = (x0 + 2*xp) <= 128;
    bool isE = (y == 256);
    float2* base = isE ? (g_E + ((size_t)bb << 16) + x0)
                       : (g_A + ((size_t)bb << 24) + ((size_t)y << 8) + x0);
    size_t zs4 = isE ? 128 : 32768;       // z-plane stride in float4 units
    float4* base4 = (float4*)base;
    float2* sl0 = s + (2*xp)*261;
    float2* sl1 = sl0 + 261;
#pragma unroll
    for (int c = 0; c < 2; ++c){
        int q = (c << 5) + u;
        int n0 = dr3(q);
        float4 v0 = make_float4(0.f,0.f,0.f,0.f), v1 = v0;
        if (valid){
            v0 = base4[(size_t)n0*zs4 + xp];
            v1 = base4[(size_t)(n0 + 64)*zs4 + xp];
        }
        float2 z2 = make_float2(0.f, 0.f);
        stage0_reg<-1>(make_float2(v0.x,v0.y), make_float2(v1.x,v1.y), z2, z2, sl0, q);
        stage0_reg<-1>(make_float2(v0.z,v0.w), make_float2(v1.z,v1.w), z2, z2, sl1, q);
    }
    fft_mid_x2<-1,3>(sl0, sl1, u);
    if (valid){
#pragma unroll
        for (int k = 0; k < 2; ++k){
            int j = (k << 5) + u;
            float2 a0,a1,a2,a3, c0,c1,c2,c3;
            fft256_last<-1>(sl0, j, a0,a1,a2,a3);
            fft256_last<-1>(sl1, j, c0,c1,c2,c3);
            base4[(size_t)j*zs4 + xp]         = make_float4(a0.x,a0.y,c0.x,c0.y);
            base4[(size_t)(j + 64)*zs4 + xp]  = make_float4(a1.x,a1.y,c1.x,c1.y);
            base4[(size_t)(j + 128)*zs4 + xp] = make_float4(a2.x,a2.y,c2.x,c2.y);
            base4[(size_t)(j + 192)*zs4 + xp] = make_float4(a3.x,a3.y,c3.x,c3.y);
        }
    }
}

// Fused Stolt z-interp + inverse X FFT. Samples ARE the stage-0 quad inputs.
__global__ void k_resample_invx(){
    __shared__ float2 s[4*260];
    int tid = threadIdx.x;
    int line = tid >> 6, t = tid & 63;
    int jy = (blockIdx.x << 2) + line;
    int jz = blockIdx.y + 1;        // 1..127
    int bb = blockIdx.z;
    int sy = jy ^ 128;
    float gz = (float)jz * (1.0f/128.0f);
    float gy = (float)(sy - 128) * (1.0f/128.0f);
    const float fk = 0.1024f;
    float gyz = fk*gy*gy + gz*gz;
    const float2* Ab = g_A + ((size_t)bb << 24);
    const float2* Eb = g_E + ((size_t)bb << 16);
    float2* sl = s + line*260;
    int ry = (jy == 128) ? 128 : ((257 - jy) & 255);
    bool useE = (jy == 129);
    float2 vq[4];
#pragma unroll
    for (int k = 0; k < 4; ++k){
        int jx = t + (k << 6);      // natural index of quad dr3(t)
        int sx = jx ^ 128;
        float gx = (float)(sx - 128) * (1.0f/128.0f);
        float gznew = sqrtf(fk*gx*gx + gyz);
        float pz = (gznew + 1.0f)*128.0f - 0.5f;    // >= 128.5
        float z0f = floorf(pz);
        float dz = pz - z0f;
        int z0u = (int)z0f - 128;                   // >= 0
        float accx = 0.f, accy = 0.f;
#pragma unroll
        for (int tz = 0; tz < 2; ++tz){
            int zp = z0u + tz;
            if (zp > 127) continue;
            float w = tz ? dz : (1.0f - dz);
            float2 v;
            if (jx <= 128){
                v = __ldg(&Ab[((size_t)zp << 16) + ((size_t)jy << 8) + (size_t)jx]);
            } else {
                int m = (jx == 129) ? 129 : (257 - jx);
                int zq = (256 - zp) & 255;
                if (useE){
                    float2 e = __ldg(&Eb[((size_t)zq << 8) + (size_t)m]);
                    v = make_float2(e.x, -e.y);
                } else {
                    float2 e = __ldg(&Ab[((size_t)zq << 16) + ((size_t)ry << 8) + (size_t)m]);
                    v = make_float2(e.x, -e.y);
                }
            }
            accx += w * v.x; accy += w * v.y;
        }
        float fac = gz / (gznew + 1e-8f) * (1.0f/256.0f);
        vq[k] = make_float2(accx * fac, accy * fac);
    }
    stage0_reg<1>(vq[0], vq[1], vq[2], vq[3], sl, dr3(t));
    fft_mid<1,64,3>(sl, t);
    float2 o0,o1,o2,o3;
    fft256_last<1>(sl, t, o0,o1,o2,o3);
    size_t o = ((size_t)bb << 24) + ((size_t)jz << 16) + ((size_t)jy << 8);
    g_B[o + t]      = o0;
    g_B[o + t + 64] = o1;
}

// Inverse Y: full 256-y input, write y<128 scaled. Column-pair layout.
// Row stride of g_B in float4 units = 128.
__global__ void k_inv_y(){
    __shared__ float2 s[16*261];
    int x0 = blockIdx.x << 4, zz = blockIdx.y + 1, bb = blockIdx.z;
    int tid = threadIdx.x, xp = tid & 7, u = tid >> 3;
    float2* base = g_B + ((size_t)bb << 24) + ((size_t)zz << 16) + x0;
    float4* base4 = (float4*)base;
    float2* sl0 = s + (2*xp)*261;
    float2* sl1 = sl0 + 261;
#pragma unroll
    for (int c = 0; c < 2; ++c){
        int q = (c << 5) + u;
        int n0 = dr3(q);
        float4 v0 = base4[(size_t)n0*128 + xp];
        float4 v1 = base4[(size_t)(n0 + 64)*128 + xp];
        float4 v2 = base4[(size_t)(n0 + 128)*128 + xp];
        float4 v3 = base4[(size_t)(n0 + 192)*128 + xp];
        stage0_reg<1>(make_float2(v0.x,v0.y), make_float2(v1.x,v1.y),
                      make_float2(v2.x,v2.y), make_float2(v3.x,v3.y), sl0, q);
        stage0_reg<1>(make_float2(v0.z,v0.w), make_float2(v1.z,v1.w),
                      make_float2(v2.z,v2.w), make_float2(v3.z,v3.w), sl1, q);
    }
    fft_mid_x2<1,3>(sl0, sl1, u);
#pragma unroll
    for (int k = 0; k < 2; ++k){
        int j = (k << 5) + u;               // < 64
        float2 a0,a1,a2,a3, c0,c1,c2,c3;
        fft256_last<1>(sl0, j, a0,a1,a2,a3);
        fft256_last<1>(sl1, j, c0,c1,c2,c3);
        const float sc = 1.f/256.f;
        base4[(size_t)j*128 + xp]        = make_float4(a0.x*sc, a0.y*sc, c0.x*sc, c0.y*sc);
        base4[(size_t)(j + 64)*128 + xp] = make_float4(a1.x*sc, a1.y*sc, c1.x*sc, c1.y*sc);
    }
}

// Inverse Z: z in [1,128) nonzero, upper half zero-padded. Writes Re to output.
__global__ void k_inv_z(float* __restrict__ out){
    __shared__ float2 s[16*261];
    int x0 = blockIdx.x << 4, y = blockIdx.y, bb = blockIdx.z;
    int tid = threadIdx.x, xp = tid & 7, u = tid >> 3;
    const float2* base = g_B + ((size_t)bb << 24) + ((size_t)y << 8) + x0;
    const float4* base4 = (const float4*)base;
    float2* sl0 = s + (2*xp)*261;
    float2* sl1 = sl0 + 261;
#pragma unroll
    for (int c = 0; c < 2; ++c){
        int q = (c << 5) + u;
        int n0 = dr3(q);
        float4 v0 = make_float4(0.f,0.f,0.f,0.f);
        if (n0 >= 1) v0 = base4[(size_t)n0*32768 + xp];
        float4 v1 = base4[(size_t)(n0 + 64)*32768 + xp];
        float2 z2 = make_float2(0.f, 0.f);
        stage0_reg<1>(make_float2(v0.x,v0.y), make_float2(v1.x,v1.y), z2, z2, sl0, q);
        stage0_reg<1>(make_float2(v0.z,v0.w), make_float2(v1.z,v1.w), z2, z2, sl1, q);
    }
    fft_mid_x2<1,3>(sl0, sl1, u);
    float* ob = out + ((size_t)bb << 21) + (size_t)y*128 + (size_t)(x0 + 2*xp);
#pragma unroll
    for (int k = 0; k < 2; ++k){
        int j = (k << 5) + u;               // < 64
        float2 a0,a1,a2,a3, c0,c1,c2,c3;
        fft256_last<1>(sl0, j, a0,a1,a2,a3);
        fft256_last<1>(sl1, j, c0,c1,c2,c3);
        const float sc = 1.f/256.f;
        *(float2*)(ob + (size_t)j*16384)        = make_float2(a0.x*sc, c0.x*sc);
        *(float2*)(ob + (size_t)(j + 64)*16384) = make_float2(a1.x*sc, c1.x*sc);
    }
}

extern "C" void kernel_launch(void* const* d_in, const int* in_sizes, int n_in,
                              void* d_out, int out_size){
    (void)in_sizes; (void)n_in; (void)out_size;
    const float* in = (const float*)d_in[0];
    float* out = (float*)d_out;

    k_fwd_x        <<<dim3(32, 128, 2), 256>>>(in);
    k_fwd_y        <<<dim3(9,  128, 2), 256>>>();
    k_fwd_z        <<<dim3(9,  257, 2), 256>>>();
    k_resample_invx<<<dim3(64, 127, 2), 256>>>();
    k_inv_y        <<<dim3(8,  127, 2), 256>>>();
    k_inv_z        <<<dim3(8,  128, 2), 256>>>(out);
}

// round 13
// speedup vs baseline: 1.5943x; 1.0073x over previous
#include <cuda_runtime.h>
#include <cstdint>

#define PI_F 3.14159265358979323846f
static __device__ __align__(16) float2 g_A[33554432];  // stenciled fwd spectrum, cols m<=129
static __device__ __align__(16) float2 g_B[33554432];  // inverse pipeline
static __device__ __align__(16) float2 g_E[131072];    // [b][z][m]: y-stencil full value @ jy=128

__device__ __forceinline__ float2 cmul(float2 a, float2 b){
    return make_float2(a.x*b.x - a.y*b.y, a.x*b.y + a.y*b.x);
}
__device__ __forceinline__ float fsqrt_approx(float x){
    float r; asm("sqrt.approx.f32 %0, %1;" : "=f"(r) : "f"(x)); return r;
}
// 3-digit base-4 reversal (quads); involution.
__device__ __forceinline__ int dr3(int q){
    return ((q & 3) << 4) | (((q >> 2) & 3) << 2) | ((q >> 4) & 3);
}
// skewed shared index: breaks 64-stride bank alignment
__device__ __forceinline__ int sidx(int p){ return p + (p >> 6); }

// Pure radix-4 butterfly (twiddles pre-applied by caller).
template<int SIGN>
__device__ __forceinline__ void bfly4(float2 a0, float2 a1, float2 a2, float2 a3,
        float2& o0, float2& o1, float2& o2, float2& o3){
    float2 t02p = make_float2(a0.x+a2.x, a0.y+a2.y);
    float2 t02m = make_float2(a0.x-a2.x, a0.y-a2.y);
    float2 t13p = make_float2(a1.x+a3.x, a1.y+a3.y);
    float2 t13m = make_float2(a1.x-a3.x, a1.y-a3.y);
    float2 jt = (SIGN<0) ? make_float2(t13m.y,-t13m.x) : make_float2(-t13m.y,t13m.x);
    o0 = make_float2(t02p.x+t13p.x, t02p.y+t13p.y);
    o1 = make_float2(t02m.x+jt.x,   t02m.y+jt.y);
    o2 = make_float2(t02p.x-t13p.x, t02p.y-t13p.y);
    o3 = make_float2(t02m.x-jt.x,   t02m.y-jt.y);
}

// Radix-4 stage 0 from registers -> shared quad q, skew-indexed (shared-FFT path).
template<int SIGN>
__device__ __forceinline__ void stage0_reg(float2 a0, float2 a1, float2 a2, float2 a3,
                                           float2* s, int q){
    float2 o0,o1,o2,o3;
    bfly4<SIGN>(a0,a1,a2,a3,o0,o1,o2,o3);
    int b4 = 4*q;
    s[sidx(b4)]   = o0;
    s[sidx(b4+1)] = o1;
    s[sidx(b4+2)] = o2;
    s[sidx(b4+3)] = o3;
}

// One radix-4 butterfly of stage st (>=1) at logical index j, skew-indexed shared.
template<int SIGN>
__device__ __forceinline__ void bfly_r4(float2* s, int j, int st){
    int L = 1 << (2*st);
    int p = j & (L - 1);
    int base = ((j >> (2*st)) << (2*st + 2)) + p;
    float ang = (float)SIGN * (2.0f*PI_F) * (float)p / (float)(4*L);
    float sn, cs; __sincosf(ang, &sn, &cs);
    float2 w1 = make_float2(cs, sn);
    float2 w2 = make_float2(cs*cs - sn*sn, 2.0f*cs*sn);
    float2 w3 = cmul(w1, w2);
    int i0 = sidx(base), i1 = sidx(base+L), i2 = sidx(base+2*L), i3 = sidx(base+3*L);
    float2 o0,o1,o2,o3;
    bfly4<SIGN>(s[i0], cmul(w1,s[i1]), cmul(w2,s[i2]), cmul(w3,s[i3]), o0,o1,o2,o3);
    s[i0] = o0; s[i1] = o1; s[i2] = o2; s[i3] = o3;
}

// Stages [1, NSTAGES) on one shared line, NT threads.
template<int SIGN, int NT, int NSTAGES>
__device__ __forceinline__ void fft_mid(float2* s, int t){
#pragma unroll
    for (int st = 1; st < NSTAGES; ++st){
        __syncthreads();
#pragma unroll
        for (int k = 0; k < 64/NT; ++k) bfly_r4<SIGN>(s, t + k*NT, st);
    }
    __syncthreads();
}

// Stages [1, NSTAGES) on a pair of shared lines, 32 threads per line-pair.
template<int SIGN, int NSTAGES>
__device__ __forceinline__ void fft_mid_x2(float2* sa, float2* sb, int u){
#pragma unroll
    for (int st = 1; st < NSTAGES; ++st){
        __syncthreads();
#pragma unroll
        for (int k = 0; k < 2; ++k){
            int j = u + (k << 5);
            bfly_r4<SIGN>(sa, j, st);
            bfly_r4<SIGN>(sb, j, st);
        }
    }
    __syncthreads();
}

// Last stage (L=64) in registers from (skewed) shared. Butterfly j in [0,64).
template<int SIGN>
__device__ __forceinline__ void fft256_last(const float2* s, int j,
        float2& o0, float2& o1, float2& o2, float2& o3){
    float ang = (float)SIGN * (2.0f*PI_F) * (float)j * (1.0f/256.0f);
    float sn, cs; __sincosf(ang, &sn, &cs);
    float2 w1 = make_float2(cs, sn);
    float2 w2 = make_float2(cs*cs - sn*sn, 2.0f*cs*sn);
    float2 w3 = cmul(w1, w2);
    bfly4<SIGN>(s[sidx(j)], cmul(w1,s[sidx(j+64)]), cmul(w2,s[sidx(j+128)]),
                cmul(w3,s[sidx(j+192)]), o0,o1,o2,o3);
}

// Forward X + prep + X-STENCIL epilogue. Block: 4 lines x 64 threads.
__global__ void k_fwd_x(const float* __restrict__ in){
    __shared__ float2 s[4*260];
    int tid = threadIdx.x;
    int l = tid >> 6, t = tid & 63;
    int y = (blockIdx.x << 2) + l;
    int zz = blockIdx.y, bb = blockIdx.z;
    float g = (float)zz * (1.0f/127.0f);
    float g2 = g*g;
    const float* row = in + (((size_t)bb*128 + zz)*128 + y)*128;
    float2* sl = s + l*260;
    {
        float v0 = sqrtf(fmaxf(row[t]*g2, 0.0f));
        float v1 = sqrtf(fmaxf(row[t + 64]*g2, 0.0f));
        float2 z2 = make_float2(0.f, 0.f);
        stage0_reg<-1>(make_float2(v0, 0.f), make_float2(v1, 0.f), z2, z2, sl, dr3(t));
    }
    fft_mid<-1,64,4>(sl, t);
    float2* outl = g_A + (((size_t)bb*256 + zz)*256 + y)*256;
#pragma unroll
    for (int h = 0; h < 2; ++h){
        int m = t + (h << 6);
        float2 a = sl[sidx((m - 1) & 255)];
        float2 c = sl[sidx(m)];
        outl[m] = make_float2(0.5f*(a.x + c.x), 0.5f*(a.y + c.y));
    }
    if (t == 0){
        float2 c = sl[sidx(128)];
        outl[128] = make_float2(0.5f*c.x, 0.5f*c.y);
    } else if (t == 1){
        float2 a = sl[sidx(127)], c = sl[sidx(128)];
        outl[129] = make_float2(0.5f*(a.x + c.x), 0.5f*(a.y + c.y));
    }
}

// Forward Y + Y-STENCIL epilogue. Column-pair layout: 8 pairs x 32 threads.
__global__ void k_fwd_y(){
    __shared__ float2 s[16*261];
    int x0 = blockIdx.x << 4, zz = blockIdx.y, bb = blockIdx.z;
    int tid = threadIdx.x, xp = tid & 7, u = tid >> 3;
    bool valid = (x0 + 2*xp) <= 128;
    float2* base = g_A + ((size_t)bb << 24) + ((size_t)zz << 16) + x0;
    float4* base4 = (float4*)base;
    float2* sl0 = s + (2*xp)*261;
    float2* sl1 = sl0 + 261;
#pragma unroll
    for (int c = 0; c < 2; ++c){
        int q = (c << 5) + u;
        int n0 = dr3(q);
        float4 v0 = make_float4(0.f,0.f,0.f,0.f), v1 = v0;
        if (valid){
            v0 = base4[(size_t)n0*128 + xp];
            v1 = base4[(size_t)(n0 + 64)*128 + xp];
        }
        float2 z2 = make_float2(0.f, 0.f);
        stage0_reg<-1>(make_float2(v0.x,v0.y), make_float2(v1.x,v1.y), z2, z2, sl0, q);
        stage0_reg<-1>(make_float2(v0.z,v0.w), make_float2(v1.z,v1.w), z2, z2, sl1, q);
    }
    fft_mid_x2<-1,4>(sl0, sl1, u);
    if (valid){
#pragma unroll
        for (int c = 0; c < 8; ++c){
            int jy = (c << 5) + u;
            float2 v0, v1;
            if (jy == 128){
                float2 c0 = sl0[sidx(128)], c1 = sl1[sidx(128)];
                v0 = make_float2(0.5f*c0.x, 0.5f*c0.y);
                v1 = make_float2(0.5f*c1.x, 0.5f*c1.y);
            } else {
                int jm = (jy - 1) & 255;
                float2 a0 = sl0[sidx(jm)], c0 = sl0[sidx(jy)];
                float2 a1 = sl1[sidx(jm)], c1 = sl1[sidx(jy)];
                v0 = make_float2(0.5f*(a0.x + c0.x), 0.5f*(a0.y + c0.y));
                v1 = make_float2(0.5f*(a1.x + c1.x), 0.5f*(a1.y + c1.y));
            }
            base4[(size_t)jy*128 + xp] = make_float4(v0.x, v0.y, v1.x, v1.y);
        }
        if (u == 0){
            float2 a0 = sl0[sidx(127)], c0 = sl0[sidx(128)];
            float2 a1 = sl1[sidx(127)], c1 = sl1[sidx(128)];
            float4* E4 = (float4*)(g_E + ((size_t)bb << 16) + ((size_t)zz << 8) + x0);
            E4[xp] = make_float4(0.5f*(a0.x + c0.x), 0.5f*(a0.y + c0.y),
                                 0.5f*(a1.x + c1.x), 0.5f*(a1.y + c1.y));
        }
    }
}

// Forward Z (merged: blockIdx.y==256 handles the g_E side buffer).
__global__ void k_fwd_z(){
    __shared__ float2 s[16*261];
    int x0 = blockIdx.x << 4, y = blockIdx.y, bb = blockIdx.z;
    int tid = threadIdx.x, xp = tid & 7, u = tid >> 3;
    bool valid = (x0 + 2*xp) <= 128;
    bool isE = (y == 256);
    float2* base = isE ? (g_E + ((size_t)bb << 16) + x0)
                       : (g_A + ((size_t)bb << 24) + ((size_t)y << 8) + x0);
    size_t zs4 = isE ? 128 : 32768;
    float4* base4 = (float4*)base;
    float2* sl0 = s + (2*xp)*261;
    float2* sl1 = sl0 + 261;
#pragma unroll
    for (int c = 0; c < 2; ++c){
        int q = (c << 5) + u;
        int n0 = dr3(q);
        float4 v0 = make_float4(0.f,0.f,0.f,0.f), v1 = v0;
        if (valid){
            v0 = base4[(size_t)n0*zs4 + xp];
            v1 = base4[(size_t)(n0 + 64)*zs4 + xp];
        }
        float2 z2 = make_float2(0.f, 0.f);
        stage0_reg<-1>(make_float2(v0.x,v0.y), make_float2(v1.x,v1.y), z2, z2, sl0, q);
        stage0_reg<-1>(make_float2(v0.z,v0.w), make_float2(v1.z,v1.w), z2, z2, sl1, q);
    }
    fft_mid_x2<-1,3>(sl0, sl1, u);
    if (valid){
#pragma unroll
        for (int k = 0; k < 2; ++k){
            int j = (k << 5) + u;
            float2 a0,a1,a2,a3, c0,c1,c2,c3;
            fft256_last<-1>(sl0, j, a0,a1,a2,a3);
            fft256_last<-1>(sl1, j, c0,c1,c2,c3);
            base4[(size_t)j*zs4 + xp]         = make_float4(a0.x,a0.y,c0.x,c0.y);
            base4[(size_t)(j + 64)*zs4 + xp]  = make_float4(a1.x,a1.y,c1.x,c1.y);
            base4[(size_t)(j + 128)*zs4 + xp] = make_float4(a2.x,a2.y,c2.x,c2.y);
            base4[(size_t)(j + 192)*zs4 + xp] = make_float4(a3.x,a3.y,c3.x,c3.y);
        }
    }
}

// Fused Stolt z-interp + inverse X FFT, REGISTER-FFT version.
// Block: 16 jy-lines x 16 threads. Thread t handles jx = t + 16k (16 samples).
// Stages 0+1 in registers, ONE shared transpose, stages 2+3 in registers.
__global__ void k_resample_invx(){
    __shared__ float2 s[16*280];
    int tid = threadIdx.x;
    int line = tid >> 4, t = tid & 15;
    int jy = (blockIdx.x << 4) + line;
    int jz = blockIdx.y + 1;        // 1..127
    int bb = blockIdx.z;
    int sy = jy ^ 128;
    float gz = (float)jz * (1.0f/128.0f);
    float gy = (float)(sy - 128) * (1.0f/128.0f);
    const float fk = 0.1024f;
    float gyz = fk*gy*gy + gz*gz;
    const float2* Ab = g_A + ((size_t)bb << 24);
    const float2* Eb = g_E + ((size_t)bb << 16);
    int ry = (jy == 128) ? 128 : ((257 - jy) & 255);
    bool useE = (jy == 129);

    // ---- sample gather: v[k] = sample(jx = t + 16k) ----
    float2 v[16];
#pragma unroll
    for (int k = 0; k < 16; ++k){
        int jx = t + (k << 4);
        int sx = jx ^ 128;
        float gx = (float)(sx - 128) * (1.0f/128.0f);
        float gznew = fsqrt_approx(fk*gx*gx + gyz);
        float pz = (gznew + 1.0f)*128.0f - 0.5f;    // >= 128.5
        float z0f = floorf(pz);
        float dz = pz - z0f;
        int z0u = (int)z0f - 128;                   // >= 0
        float accx = 0.f, accy = 0.f;
#pragma unroll
        for (int tz = 0; tz < 2; ++tz){
            int zp = z0u + tz;
            if (zp > 127) continue;
            float w = tz ? dz : (1.0f - dz);
            float2 vv;
            if (jx <= 128){
                vv = __ldg(&Ab[((size_t)zp << 16) + ((size_t)jy << 8) + (size_t)jx]);
            } else {
                int m = (jx == 129) ? 129 : (257 - jx);
                int zq = (256 - zp) & 255;
                float2 e = useE ? __ldg(&Eb[((size_t)zq << 8) + (size_t)m])
                                : __ldg(&Ab[((size_t)zq << 16) + ((size_t)ry << 8) + (size_t)m]);
                vv = make_float2(e.x, -e.y);
            }
            accx += w*vv.x; accy += w*vv.y;
        }
        float fac = __fdividef(gz, gznew + 1e-8f) * (1.0f/256.0f);
        v[k] = make_float2(accx*fac, accy*fac);
    }

    // ---- stage 0 in registers (no twiddle). Butterfly k0 on v[k0,k0+4,k0+8,k0+12],
    //      output L[4k0+r] stored at v-slot [k0+4r] (so stage1 quads are contiguous).
#pragma unroll
    for (int k0 = 0; k0 < 4; ++k0){
        bfly4<1>(v[k0], v[k0+4], v[k0+8], v[k0+12],
                 v[k0], v[k0+4], v[k0+8], v[k0+12]);
    }
    // ---- stage 1 in registers, compile-time twiddles. Butterfly p on v[4p..4p+3].
    {
        const float TC[4] = {1.0f, 0.92387953251f, 0.70710678119f, 0.38268343236f};
        const float TS[4] = {0.0f, 0.38268343236f, 0.70710678119f, 0.92387953251f};
#pragma unroll
        for (int p = 0; p < 4; ++p){
            float2 w1 = make_float2(TC[p], TS[p]);       // SIGN=+1
            float2 w2 = cmul(w1, w1);
            float2 w3 = cmul(w1, w2);
            bfly4<1>(v[4*p], cmul(w1, v[4*p+1]), cmul(w2, v[4*p+2]), cmul(w3, v[4*p+3]),
                     v[4*p], v[4*p+1], v[4*p+2], v[4*p+3]);
        }
    }
    // ---- transpose through shared. Thread t holds global positions 16*sig + i,
    //      sig = 4(t&3)+(t>>2); L[i] lives in v[4*(i&3) + (i>>2)].
    {
        float2* SL = s + line*280;
        int sg = 17*(4*(t & 3) + (t >> 2));
#pragma unroll
        for (int i = 0; i < 16; ++i)
            SL[sg + i] = v[4*(i & 3) + (i >> 2)];
        __syncthreads();
#pragma unroll
        for (int m = 0; m < 16; ++m)
            v[m] = SL[17*m + t];          // position 16m + t
    }
    // ---- stage 2 in registers: butterfly h on v[4h..4h+3], twiddle p = t (one sincos).
    {
        float sn, cs; __sincosf((2.0f*PI_F/64.0f)*(float)t, &sn, &cs);
        float2 w1 = make_float2(cs, sn);
        float2 w2 = cmul(w1, w1);
        float2 w3 = cmul(w1, w2);
#pragma unroll
        for (int h = 0; h < 4; ++h){
            bfly4<1>(v[4*h], cmul(w1, v[4*h+1]), cmul(w2, v[4*h+2]), cmul(w3, v[4*h+3]),
                     v[4*h], v[4*h+1], v[4*h+2], v[4*h+3]);
        }
    }
    // ---- stage 3 in registers + write x<128. Butterfly m0 on v[m0, m0+4, m0+8, m0+12],
    //      twiddle p = 16*m0 + t  ->  w1 = wb * c(m0), wb = e^{2pi i t/256}.
    {
        float sn, cs; __sincosf((2.0f*PI_F/256.0f)*(float)t, &sn, &cs);
        float2 wb = make_float2(cs, sn);
        const float TC[4] = {1.0f, 0.92387953251f, 0.70710678119f, 0.38268343236f};
        const float TS[4] = {0.0f, 0.38268343236f, 0.70710678119f, 0.92387953251f};
        float2* outl = g_B + ((size_t)bb << 24) + ((size_t)jz << 16) + ((size_t)jy << 8);
#pragma unroll
        for (int m0 = 0; m0 < 4; ++m0){
            float2 w1 = cmul(wb, make_float2(TC[m0], TS[m0]));
            float2 w2 = cmul(w1, w1);
            float2 w3 = cmul(w1, w2);
            float2 o0,o1,o2,o3;
            bfly4<1>(v[m0], cmul(w1, v[m0+4]), cmul(w2, v[m0+8]), cmul(w3, v[m0+12]),
                     o0,o1,o2,o3);
            outl[16*m0 + t]      = o0;     // x = 16*m0 + t      (< 64)
            outl[16*m0 + 64 + t] = o1;     // x = 16*(m0+4) + t  (< 128)
            // o2, o3 land at x >= 128: discarded by the final crop.
        }
    }
}

// Inverse Y: full 256-y input, write y<128 scaled. Column-pair layout.
__global__ void k_inv_y(){
    __shared__ float2 s[16*261];
    int x0 = blockIdx.x << 4, zz = blockIdx.y + 1, bb = blockIdx.z;
    int tid = threadIdx.x, xp = tid & 7, u = tid >> 3;
    float2* base = g_B + ((size_t)bb << 24) + ((size_t)zz << 16) + x0;
    float4* base4 = (float4*)base;
    float2* sl0 = s + (2*xp)*261;
    float2* sl1 = sl0 + 261;
#pragma unroll
    for (int c = 0; c < 2; ++c){
        int q = (c << 5) + u;
        int n0 = dr3(q);
        float4 v0 = base4[(size_t)n0*128 + xp];
        float4 v1 = base4[(size_t)(n0 + 64)*128 + xp];
        float4 v2 = base4[(size_t)(n0 + 128)*128 + xp];
        float4 v3 = base4[(size_t)(n0 + 192)*128 + xp];
        stage0_reg<1>(make_float2(v0.x,v0.y), make_float2(v1.x,v1.y),
                      make_float2(v2.x,v2.y), make_float2(v3.x,v3.y), sl0, q);
        stage0_reg<1>(make_float2(v0.z,v0.w), make_float2(v1.z,v1.w),
                      make_float2(v2.z,v2.w), make_float2(v3.z,v3.w), sl1, q);
    }
    fft_mid_x2<1,3>(sl0, sl1, u);
#pragma unroll
    for (int k = 0; k < 2; ++k){
        int j = (k << 5) + u;               // < 64
        float2 a0,a1,a2,a3, c0,c1,c2,c3;
        fft256_last<1>(sl0, j, a0,a1,a2,a3);
        fft256_last<1>(sl1, j, c0,c1,c2,c3);
        const float sc = 1.f/256.f;
        base4[(size_t)j*128 + xp]        = make_float4(a0.x*sc, a0.y*sc, c0.x*sc, c0.y*sc);
        base4[(size_t)(j + 64)*128 + xp] = make_float4(a1.x*sc, a1.y*sc, c1.x*sc, c1.y*sc);
    }
}

// Inverse Z: z in [1,128) nonzero, upper half zero-padded. Writes Re to output.
__global__ void k_inv_z(float* __restrict__ out){
    __shared__ float2 s[16*261];
    int x0 = blockIdx.x << 4, y = blockIdx.y, bb = blockIdx.z;
    int tid = threadIdx.x, xp = tid & 7, u = tid >> 3;
    const float2* base = g_B + ((size_t)bb << 24) + ((size_t)y << 8) + x0;
    const float4* base4 = (const float4*)base;
    float2* sl0 = s + (2*xp)*261;
    float2* sl1 = sl0 + 261;
#pragma unroll
    for (int c = 0; c < 2; ++c){
        int q = (c << 5) + u;
        int n0 = dr3(q);
        float4 v0 = make_float4(0.f,0.f,0.f,0.f);
        if (n0 >= 1) v0 = base4[(size_t)n0*32768 + xp];
        float4 v1 = base4[(size_t)(n0 + 64)*32768 + xp];
        float2 z2 = make_float2(0.f, 0.f);
        stage0_reg<1>(make_float2(v0.x,v0.y), make_float2(v1.x,v1.y), z2, z2, sl0, q);
        stage0_reg<1>(make_float2(v0.z,v0.w), make_float2(v1.z,v1.w), z2, z2, sl1, q);
    }
    fft_mid_x2<1,3>(sl0, sl1, u);
    float* ob = out + ((size_t)bb << 21) + (size_t)y*128 + (size_t)(x0 + 2*xp);
#pragma unroll
    for (int k = 0; k < 2; ++k){
        int j = (k << 5) + u;               // < 64
        float2 a0,a1,a2,a3, c0,c1,c2,c3;
        fft256_last<1>(sl0, j, a0,a1,a2,a3);
        fft256_last<1>(sl1, j, c0,c1,c2,c3);
        const float sc = 1.f/256.f;
        *(float2*)(ob + (size_t)j*16384)        = make_float2(a0.x*sc, c0.x*sc);
        *(float2*)(ob + (size_t)(j + 64)*16384) = make_float2(a1.x*sc, c1.x*sc);
    }
}

extern "C" void kernel_launch(void* const* d_in, const int* in_sizes, int n_in,
                              void* d_out, int out_size){
    (void)in_sizes; (void)n_in; (void)out_size;
    const float* in = (const float*)d_in[0];
    float* out = (float*)d_out;

    k_fwd_x        <<<dim3(32, 128, 2), 256>>>(in);
    k_fwd_y        <<<dim3(9,  128, 2), 256>>>();
    k_fwd_z        <<<dim3(9,  257, 2), 256>>>();
    k_resample_invx<<<dim3(16, 127, 2), 256>>>();
    k_inv_y        <<<dim3(8,  127, 2), 256>>>();
    k_inv_z        <<<dim3(8,  128, 2), 256>>>(out);
}

// round 14
// speedup vs baseline: 1.6687x; 1.0466x over previous
#include <cuda_runtime.h>
#include <cstdint>

#define PI_F 3.14159265358979323846f
static __device__ __align__(16) float2 g_A[33554432];  // stenciled fwd spectrum, cols m<=129
static __device__ __align__(16) float2 g_B[33554432];  // inverse pipeline
static __device__ __align__(16) float2 g_E[131072];    // [b][z][m]: y-stencil full value @ jy=128

__device__ __forceinline__ float2 cmul(float2 a, float2 b){
    return make_float2(a.x*b.x - a.y*b.y, a.x*b.y + a.y*b.x);
}
__device__ __forceinline__ float fsqrt_approx(float x){
    float r; asm("sqrt.approx.f32 %0, %1;" : "=f"(r) : "f"(x)); return r;
}
// 3-digit base-4 reversal (quads); involution.
__device__ __forceinline__ int dr3(int q){
    return ((q & 3) << 4) | (((q >> 2) & 3) << 2) | ((q >> 4) & 3);
}
// skewed shared index: breaks 64-stride bank alignment
__device__ __forceinline__ int sidx(int p){ return p + (p >> 6); }

// Pure radix-4 butterfly (twiddles pre-applied by caller).
template<int SIGN>
__device__ __forceinline__ void bfly4(float2 a0, float2 a1, float2 a2, float2 a3,
        float2& o0, float2& o1, float2& o2, float2& o3){
    float2 t02p = make_float2(a0.x+a2.x, a0.y+a2.y);
    float2 t02m = make_float2(a0.x-a2.x, a0.y-a2.y);
    float2 t13p = make_float2(a1.x+a3.x, a1.y+a3.y);
    float2 t13m = make_float2(a1.x-a3.x, a1.y-a3.y);
    float2 jt = (SIGN<0) ? make_float2(t13m.y,-t13m.x) : make_float2(-t13m.y,t13m.x);
    o0 = make_float2(t02p.x+t13p.x, t02p.y+t13p.y);
    o1 = make_float2(t02m.x+jt.x,   t02m.y+jt.y);
    o2 = make_float2(t02p.x-t13p.x, t02p.y-t13p.y);
    o3 = make_float2(t02m.x-jt.x,   t02m.y-jt.y);
}

// Radix-4 stage 0 from registers -> shared quad q, skew-indexed (shared-FFT path).
template<int SIGN>
__device__ __forceinline__ void stage0_reg(float2 a0, float2 a1, float2 a2, float2 a3,
                                           float2* s, int q){
    float2 o0,o1,o2,o3;
    bfly4<SIGN>(a0,a1,a2,a3,o0,o1,o2,o3);
    int b4 = 4*q;
    s[sidx(b4)]   = o0;
    s[sidx(b4+1)] = o1;
    s[sidx(b4+2)] = o2;
    s[sidx(b4+3)] = o3;
}

// One radix-4 butterfly of stage st (>=1) at logical index j, skew-indexed shared.
template<int SIGN>
__device__ __forceinline__ void bfly_r4(float2* s, int j, int st){
    int L = 1 << (2*st);
    int p = j & (L - 1);
    int base = ((j >> (2*st)) << (2*st + 2)) + p;
    float ang = (float)SIGN * (2.0f*PI_F) * (float)p / (float)(4*L);
    float sn, cs; __sincosf(ang, &sn, &cs);
    float2 w1 = make_float2(cs, sn);
    float2 w2 = make_float2(cs*cs - sn*sn, 2.0f*cs*sn);
    float2 w3 = cmul(w1, w2);
    int i0 = sidx(base), i1 = sidx(base+L), i2 = sidx(base+2*L), i3 = sidx(base+3*L);
    float2 o0,o1,o2,o3;
    bfly4<SIGN>(s[i0], cmul(w1,s[i1]), cmul(w2,s[i2]), cmul(w3,s[i3]), o0,o1,o2,o3);
    s[i0] = o0; s[i1] = o1; s[i2] = o2; s[i3] = o3;
}

// Stages [1, NSTAGES) on one shared line, NT threads.
template<int SIGN, int NT, int NSTAGES>
__device__ __forceinline__ void fft_mid(float2* s, int t){
#pragma unroll
    for (int st = 1; st < NSTAGES; ++st){
        __syncthreads();
#pragma unroll
        for (int k = 0; k < 64/NT; ++k) bfly_r4<SIGN>(s, t + k*NT, st);
    }
    __syncthreads();
}

// Stages [1, NSTAGES) on a pair of shared lines, 32 threads per line-pair.
template<int SIGN, int NSTAGES>
__device__ __forceinline__ void fft_mid_x2(float2* sa, float2* sb, int u){
#pragma unroll
    for (int st = 1; st < NSTAGES; ++st){
        __syncthreads();
#pragma unroll
        for (int k = 0; k < 2; ++k){
            int j = u + (k << 5);
            bfly_r4<SIGN>(sa, j, st);
            bfly_r4<SIGN>(sb, j, st);
        }
    }
    __syncthreads();
}

// Last stage (L=64) in registers from (skewed) shared. Butterfly j in [0,64).
template<int SIGN>
__device__ __forceinline__ void fft256_last(const float2* s, int j,
        float2& o0, float2& o1, float2& o2, float2& o3){
    float ang = (float)SIGN * (2.0f*PI_F) * (float)j * (1.0f/256.0f);
    float sn, cs; __sincosf(ang, &sn, &cs);
    float2 w1 = make_float2(cs, sn);
    float2 w2 = make_float2(cs*cs - sn*sn, 2.0f*cs*sn);
    float2 w3 = cmul(w1, w2);
    bfly4<SIGN>(s[sidx(j)], cmul(w1,s[sidx(j+64)]), cmul(w2,s[sidx(j+128)]),
                cmul(w3,s[sidx(j+192)]), o0,o1,o2,o3);
}

// Forward X + prep + X-STENCIL epilogue. Block: 4 lines x 64 threads.
__global__ void __launch_bounds__(256, 6) k_fwd_x(const float* __restrict__ in){
    __shared__ float2 s[4*260];
    int tid = threadIdx.x;
    int l = tid >> 6, t = tid & 63;
    int y = (blockIdx.x << 2) + l;
    int zz = blockIdx.y, bb = blockIdx.z;
    float g = (float)zz * (1.0f/127.0f);
    float g2 = g*g;
    const float* row = in + (((size_t)bb*128 + zz)*128 + y)*128;
    float2* sl = s + l*260;
    {
        float v0 = sqrtf(fmaxf(row[t]*g2, 0.0f));
        float v1 = sqrtf(fmaxf(row[t + 64]*g2, 0.0f));
        float2 z2 = make_float2(0.f, 0.f);
        stage0_reg<-1>(make_float2(v0, 0.f), make_float2(v1, 0.f), z2, z2, sl, dr3(t));
    }
    fft_mid<-1,64,4>(sl, t);
    float2* outl = g_A + (((size_t)bb*256 + zz)*256 + y)*256;
#pragma unroll
    for (int h = 0; h < 2; ++h){
        int m = t + (h << 6);
        float2 a = sl[sidx((m - 1) & 255)];
        float2 c = sl[sidx(m)];
        outl[m] = make_float2(0.5f*(a.x + c.x), 0.5f*(a.y + c.y));
    }
    if (t == 0){
        float2 c = sl[sidx(128)];
        outl[128] = make_float2(0.5f*c.x, 0.5f*c.y);
    } else if (t == 1){
        float2 a = sl[sidx(127)], c = sl[sidx(128)];
        outl[129] = make_float2(0.5f*(a.x + c.x), 0.5f*(a.y + c.y));
    }
}

// Forward Y + Y-STENCIL epilogue. Column-pair layout: 8 pairs x 32 threads.
__global__ void __launch_bounds__(256, 6) k_fwd_y(){
    __shared__ float2 s[16*261];
    int x0 = blockIdx.x << 4, zz = blockIdx.y, bb = blockIdx.z;
    int tid = threadIdx.x, xp = tid & 7, u = tid >> 3;
    bool valid = (x0 + 2*xp) <= 128;
    float2* base = g_A + ((size_t)bb << 24) + ((size_t)zz << 16) + x0;
    float4* base4 = (float4*)base;
    float2* sl0 = s + (2*xp)*261;
    float2* sl1 = sl0 + 261;
#pragma unroll
    for (int c = 0; c < 2; ++c){
        int q = (c << 5) + u;
        int n0 = dr3(q);
        float4 v0 = make_float4(0.f,0.f,0.f,0.f), v1 = v0;
        if (valid){
            v0 = base4[(size_t)n0*128 + xp];
            v1 = base4[(size_t)(n0 + 64)*128 + xp];
        }
        float2 z2 = make_float2(0.f, 0.f);
        stage0_reg<-1>(make_float2(v0.x,v0.y), make_float2(v1.x,v1.y), z2, z2, sl0, q);
        stage0_reg<-1>(make_float2(v0.z,v0.w), make_float2(v1.z,v1.w), z2, z2, sl1, q);
    }
    fft_mid_x2<-1,4>(sl0, sl1, u);
    if (valid){
#pragma unroll
        for (int c = 0; c < 8; ++c){
            int jy = (c << 5) + u;
            float2 v0, v1;
            if (jy == 128){
                float2 c0 = sl0[sidx(128)], c1 = sl1[sidx(128)];
                v0 = make_float2(0.5f*c0.x, 0.5f*c0.y);
                v1 = make_float2(0.5f*c1.x, 0.5f*c1.y);
            } else {
                int jm = (jy - 1) & 255;
                float2 a0 = sl0[sidx(jm)], c0 = sl0[sidx(jy)];
                float2 a1 = sl1[sidx(jm)], c1 = sl1[sidx(jy)];
                v0 = make_float2(0.5f*(a0.x + c0.x), 0.5f*(a0.y + c0.y));
                v1 = make_float2(0.5f*(a1.x + c1.x), 0.5f*(a1.y + c1.y));
            }
            base4[(size_t)jy*128 + xp] = make_float4(v0.x, v0.y, v1.x, v1.y);
        }
        if (u == 0){
            float2 a0 = sl0[sidx(127)], c0 = sl0[sidx(128)];
            float2 a1 = sl1[sidx(127)], c1 = sl1[sidx(128)];
            float4* E4 = (float4*)(g_E + ((size_t)bb << 16) + ((size_t)zz << 8) + x0);
            E4[xp] = make_float4(0.5f*(a0.x + c0.x), 0.5f*(a0.y + c0.y),
                                 0.5f*(a1.x + c1.x), 0.5f*(a1.y + c1.y));
        }
    }
}

// Forward Z (merged: blockIdx.y==256 handles the g_E side buffer).
__global__ void __launch_bounds__(256, 6) k_fwd_z(){
    __shared__ float2 s[16*261];
    int x0 = blockIdx.x << 4, y = blockIdx.y, bb = blockIdx.z;
    int tid = threadIdx.x, xp = tid & 7, u = tid >> 3;
    bool valid = (x0 + 2*xp) <= 128;
    bool isE = (y == 256);
    float2* base = isE ? (g_E + ((size_t)bb << 16) + x0)
                       : (g_A + ((size_t)bb << 24) + ((size_t)y << 8) + x0);
    size_t zs4 = isE ? 128 : 32768;
    float4* base4 = (float4*)base;
    float2* sl0 = s + (2*xp)*261;
    float2* sl1 = sl0 + 261;
#pragma unroll
    for (int c = 0; c < 2; ++c){
        int q = (c << 5) + u;
        int n0 = dr3(q);
        float4 v0 = make_float4(0.f,0.f,0.f,0.f), v1 = v0;
        if (valid){
            v0 = base4[(size_t)n0*zs4 + xp];
            v1 = base4[(size_t)(n0 + 64)*zs4 + xp];
        }
        float2 z2 = make_float2(0.f, 0.f);
        stage0_reg<-1>(make_float2(v0.x,v0.y), make_float2(v1.x,v1.y), z2, z2, sl0, q);
        stage0_reg<-1>(make_float2(v0.z,v0.w), make_float2(v1.z,v1.w), z2, z2, sl1, q);
    }
    fft_mid_x2<-1,3>(sl0, sl1, u);
    if (valid){
#pragma unroll
        for (int k = 0; k < 2; ++k){
            int j = (k << 5) + u;
            float2 a0,a1,a2,a3, c0,c1,c2,c3;
            fft256_last<-1>(sl0, j, a0,a1,a2,a3);
            fft256_last<-1>(sl1, j, c0,c1,c2,c3);
            base4[(size_t)j*zs4 + xp]         = make_float4(a0.x,a0.y,c0.x,c0.y);
            base4[(size_t)(j + 64)*zs4 + xp]  = make_float4(a1.x,a1.y,c1.x,c1.y);
            base4[(size_t)(j + 128)*zs4 + xp] = make_float4(a2.x,a2.y,c2.x,c2.y);
            base4[(size_t)(j + 192)*zs4 + xp] = make_float4(a3.x,a3.y,c3.x,c3.y);
        }
    }
}

// Fused Stolt z-interp + inverse X FFT, REGISTER-FFT version.
// Block: 16 jy-lines x 16 threads. Thread t handles jx = t + 16k (16 samples).
// Stages 0+1 in registers, ONE shared transpose, stages 2+3 in registers.
__global__ void __launch_bounds__(256, 5) k_resample_invx(){
    __shared__ float2 s[16*272];
    int tid = threadIdx.x;
    int line = tid >> 4, t = tid & 15;
    int jy = (blockIdx.x << 4) + line;
    int jz = blockIdx.y + 1;        // 1..127
    int bb = blockIdx.z;
    int sy = jy ^ 128;
    float gz = (float)jz * (1.0f/128.0f);
    float gy = (float)(sy - 128) * (1.0f/128.0f);
    const float fk = 0.1024f;
    float gyz = fk*gy*gy + gz*gz;
    const float2* Ab = g_A + ((size_t)bb << 24);
    const float2* Eb = g_E + ((size_t)bb << 16);
    int ry = (jy == 128) ? 128 : ((257 - jy) & 255);
    bool useE = (jy == 129);

    // ---- sample gather: v[k] = sample(jx = t + 16k) ----
    float2 v[16];
#pragma unroll
    for (int k = 0; k < 16; ++k){
        int jx = t + (k << 4);
        int sx = jx ^ 128;
        float gx = (float)(sx - 128) * (1.0f/128.0f);
        float gznew = fsqrt_approx(fk*gx*gx + gyz);
        float pz = (gznew + 1.0f)*128.0f - 0.5f;    // >= 128.5
        float z0f = floorf(pz);
        float dz = pz - z0f;
        int z0u = (int)z0f - 128;                   // >= 0
        float accx = 0.f, accy = 0.f;
#pragma unroll
        for (int tz = 0; tz < 2; ++tz){
            int zp = z0u + tz;
            if (zp > 127) continue;
            float w = tz ? dz : (1.0f - dz);
            float2 vv;
            if (jx <= 128){
                vv = __ldg(&Ab[((size_t)zp << 16) + ((size_t)jy << 8) + (size_t)jx]);
            } else {
                int m = (jx == 129) ? 129 : (257 - jx);
                int zq = (256 - zp) & 255;
                float2 e = useE ? __ldg(&Eb[((size_t)zq << 8) + (size_t)m])
                                : __ldg(&Ab[((size_t)zq << 16) + ((size_t)ry << 8) + (size_t)m]);
                vv = make_float2(e.x, -e.y);
            }
            accx += w*vv.x; accy += w*vv.y;
        }
        float fac = __fdividef(gz, gznew + 1e-8f) * (1.0f/256.0f);
        v[k] = make_float2(accx*fac, accy*fac);
    }

    // ---- stage 0 in registers (no twiddle). Output L[4k0+r] at v-slot [k0+4r].
#pragma unroll
    for (int k0 = 0; k0 < 4; ++k0){
        bfly4<1>(v[k0], v[k0+4], v[k0+8], v[k0+12],
                 v[k0], v[k0+4], v[k0+8], v[k0+12]);
    }
    // ---- stage 1 in registers, compile-time twiddles.
    {
        const float TC[4] = {1.0f, 0.92387953251f, 0.70710678119f, 0.38268343236f};
        const float TS[4] = {0.0f, 0.38268343236f, 0.70710678119f, 0.92387953251f};
#pragma unroll
        for (int p = 0; p < 4; ++p){
            float2 w1 = make_float2(TC[p], TS[p]);       // SIGN=+1
            float2 w2 = cmul(w1, w1);
            float2 w3 = cmul(w1, w2);
            bfly4<1>(v[4*p], cmul(w1, v[4*p+1]), cmul(w2, v[4*p+2]), cmul(w3, v[4*p+3]),
                     v[4*p], v[4*p+1], v[4*p+2], v[4*p+3]);
        }
    }
    // ---- transpose through shared.
    {
        float2* SL = s + line*272;
        int sg = 17*(4*(t & 3) + (t >> 2));
#pragma unroll
        for (int i = 0; i < 16; ++i)
            SL[sg + i] = v[4*(i & 3) + (i >> 2)];
        __syncthreads();
#pragma unroll
        for (int m = 0; m < 16; ++m)
            v[m] = SL[17*m + t];          // position 16m + t
    }
    // ---- stage 2 in registers (one sincos).
    {
        float sn, cs; __sincosf((2.0f*PI_F/64.0f)*(float)t, &sn, &cs);
        float2 w1 = make_float2(cs, sn);
        float2 w2 = cmul(w1, w1);
        float2 w3 = cmul(w1, w2);
#pragma unroll
        for (int h = 0; h < 4; ++h){
            bfly4<1>(v[4*h], cmul(w1, v[4*h+1]), cmul(w2, v[4*h+2]), cmul(w3, v[4*h+3]),
                     v[4*h], v[4*h+1], v[4*h+2], v[4*h+3]);
        }
    }
    // ---- stage 3 in registers + write x<128.
    {
        float sn, cs; __sincosf((2.0f*PI_F/256.0f)*(float)t, &sn, &cs);
        float2 wb = make_float2(cs, sn);
        const float TC[4] = {1.0f, 0.92387953251f, 0.70710678119f, 0.38268343236f};
        const float TS[4] = {0.0f, 0.38268343236f, 0.70710678119f, 0.92387953251f};
        float2* outl = g_B + ((size_t)bb << 24) + ((size_t)jz << 16) + ((size_t)jy << 8);
#pragma unroll
        for (int m0 = 0; m0 < 4; ++m0){
            float2 w1 = cmul(wb, make_float2(TC[m0], TS[m0]));
            float2 w2 = cmul(w1, w1);
            float2 w3 = cmul(w1, w2);
            float2 o0,o1,o2,o3;
            bfly4<1>(v[m0], cmul(w1, v[m0+4]), cmul(w2, v[m0+8]), cmul(w3, v[m0+12]),
                     o0,o1,o2,o3);
            outl[16*m0 + t]      = o0;     // x = 16*m0 + t      (< 64)
            outl[16*m0 + 64 + t] = o1;     // x = 16*(m0+4) + t  (< 128)
        }
    }
}

// Inverse Y: full 256-y input, write y<128 scaled. Column-pair layout.
__global__ void __launch_bounds__(256, 6) k_inv_y(){
    __shared__ float2 s[16*261];
    int x0 = blockIdx.x << 4, zz = blockIdx.y + 1, bb = blockIdx.z;
    int tid = threadIdx.x, xp = tid & 7, u = tid >> 3;
    float2* base = g_B + ((size_t)bb << 24) + ((size_t)zz << 16) + x0;
    float4* base4 = (float4*)base;
    float2* sl0 = s + (2*xp)*261;
    float2* sl1 = sl0 + 261;
#pragma unroll
    for (int c = 0; c < 2; ++c){
        int q = (c << 5) + u;
        int n0 = dr3(q);
        float4 v0 = base4[(size_t)n0*128 + xp];
        float4 v1 = base4[(size_t)(n0 + 64)*128 + xp];
        float4 v2 = base4[(size_t)(n0 + 128)*128 + xp];
        float4 v3 = base4[(size_t)(n0 + 192)*128 + xp];
        stage0_reg<1>(make_float2(v0.x,v0.y), make_float2(v1.x,v1.y),
                      make_float2(v2.x,v2.y), make_float2(v3.x,v3.y), sl0, q);
        stage0_reg<1>(make_float2(v0.z,v0.w), make_float2(v1.z,v1.w),
                      make_float2(v2.z,v2.w), make_float2(v3.z,v3.w), sl1, q);
    }
    fft_mid_x2<1,3>(sl0, sl1, u);
#pragma unroll
    for (int k = 0; k < 2; ++k){
        int j = (k << 5) + u;               // < 64
        float2 a0,a1,a2,a3, c0,c1,c2,c3;
        fft256_last<1>(sl0, j, a0,a1,a2,a3);
        fft256_last<1>(sl1, j, c0,c1,c2,c3);
        const float sc = 1.f/256.f;
        base4[(size_t)j*128 + xp]        = make_float4(a0.x*sc, a0.y*sc, c0.x*sc, c0.y*sc);
        base4[(size_t)(j + 64)*128 + xp] = make_float4(a1.x*sc, a1.y*sc, c1.x*sc, c1.y*sc);
    }
}

// Inverse Z: z in [1,128) nonzero, upper half zero-padded. Writes Re to output.
__global__ void __launch_bounds__(256, 6) k_inv_z(float* __restrict__ out){
    __shared__ float2 s[16*261];
    int x0 = blockIdx.x << 4, y = blockIdx.y, bb = blockIdx.z;
    int tid = threadIdx.x, xp = tid & 7, u = tid >> 3;
    const float2* base = g_B + ((size_t)bb << 24) + ((size_t)y << 8) + x0;
    const float4* base4 = (const float4*)base;
    float2* sl0 = s + (2*xp)*261;
    float2* sl1 = sl0 + 261;
#pragma unroll
    for (int c = 0; c < 2; ++c){
        int q = (c << 5) + u;
        int n0 = dr3(q);
        float4 v0 = make_float4(0.f,0.f,0.f,0.f);
        if (n0 >= 1) v0 = base4[(size_t)n0*32768 + xp];
        float4 v1 = base4[(size_t)(n0 + 64)*32768 + xp];
        float2 z2 = make_float2(0.f, 0.f);
        stage0_reg<1>(make_float2(v0.x,v0.y), make_float2(v1.x,v1.y), z2, z2, sl0, q);
        stage0_reg<1>(make_float2(v0.z,v0.w), make_float2(v1.z,v1.w), z2, z2, sl1, q);
    }
    fft_mid_x2<1,3>(sl0, sl1, u);
    float* ob = out + ((size_t)bb << 21) + (size_t)y*128 + (size_t)(x0 + 2*xp);
#pragma unroll
    for (int k = 0; k < 2; ++k){
        int j = (k << 5) + u;               // < 64
        float2 a0,a1,a2,a3, c0,c1,c2,c3;
        fft256_last<1>(sl0, j, a0,a1,a2,a3);
        fft256_last<1>(sl1, j, c0,c1,c2,c3);
        const float sc = 1.f/256.f;
        *(float2*)(ob + (size_t)j*16384)        = make_float2(a0.x*sc, c0.x*sc);
        *(float2*)(ob + (size_t)(j + 64)*16384) = make_float2(a1.x*sc, c1.x*sc);
    }
}

extern "C" void kernel_launch(void* const* d_in, const int* in_sizes, int n_in,
                              void* d_out, int out_size){
    (void)in_sizes; (void)n_in; (void)out_size;
    const float* in = (const float*)d_in[0];
    float* out = (float*)d_out;

    k_fwd_x        <<<dim3(32, 128, 2), 256>>>(in);
    k_fwd_y        <<<dim3(9,  128, 2), 256>>>();
    k_fwd_z        <<<dim3(9,  257, 2), 256>>>();
    k_resample_invx<<<dim3(16, 127, 2), 256>>>();
    k_inv_y        <<<dim3(8,  127, 2), 256>>>();
    k_inv_z        <<<dim3(8,  128, 2), 256>>>(out);
}